// round 9
// baseline (speedup 1.0000x reference)
#include <cuda_runtime.h>
#include <cuda_bf16.h>
#include <mma.h>
#include <cstdint>

using namespace nvcuda;

#define Bn   4
#define Cc   256
#define Hh   64
#define Ww   64
#define HW   4096
#define NP   16384
#define EPSV 1e-5f
#define QSCALE 0.0625f

// ---------------------------------------------------------------------------
// Scratch
// ---------------------------------------------------------------------------
__device__ float g_q[NP * Cc];
__device__ float g_k[NP * Cc];
__device__ float g_v[NP * Cc];
__device__ __nv_bfloat16 g_a_hi[NP * Cc];
__device__ __nv_bfloat16 g_a_lo[NP * Cc];
__device__ __nv_bfloat16 g_c_hi[NP * Cc];
__device__ __nv_bfloat16 g_c_lo[NP * Cc];
__device__ __nv_bfloat16 g_w_hi[4 * Cc * Cc];
__device__ __nv_bfloat16 g_w_lo[4 * Cc * Cc];
__device__ float g_mean[Bn * Cc];
__device__ float g_rstd[Bn * Cc];

// ---------------------------------------------------------------------------
__device__ __forceinline__ uint32_t smem_u32(const void* p) {
    uint32_t a;
    asm("{ .reg .u64 t; cvta.to.shared.u64 t, %1; cvt.u32.u64 %0, t; }" : "=r"(a) : "l"(p));
    return a;
}
__device__ __forceinline__ void cp16(uint32_t dst, const void* src) {
    asm volatile("cp.async.ca.shared.global [%0], [%1], 16;" :: "r"(dst), "l"(src));
}
#define CP_COMMIT() asm volatile("cp.async.commit_group;" ::: "memory")
#define CP_WAIT1()  asm volatile("cp.async.wait_group 1;" ::: "memory")
#define CP_WAIT0()  asm volatile("cp.async.wait_group 0;" ::: "memory")

// ---------------------------------------------------------------------------
// Kernel 1: per-(b,c)-plane mean / rstd
// ---------------------------------------------------------------------------
__global__ void ln_stats_kernel(const float* __restrict__ x) {
    int plane = blockIdx.x;
    const float* p = x + (size_t)plane * HW;
    float s = 0.f, ss = 0.f;
    for (int i = threadIdx.x; i < HW; i += 256) {
        float v = p[i];
        s += v; ss += v * v;
    }
    #pragma unroll
    for (int o = 16; o; o >>= 1) {
        s  += __shfl_xor_sync(0xffffffffu, s,  o);
        ss += __shfl_xor_sync(0xffffffffu, ss, o);
    }
    __shared__ float sh1[8], sh2[8];
    int wid = threadIdx.x >> 5, ln = threadIdx.x & 31;
    if (ln == 0) { sh1[wid] = s; sh2[wid] = ss; }
    __syncthreads();
    if (threadIdx.x < 8) {
        s = sh1[threadIdx.x]; ss = sh2[threadIdx.x];
        #pragma unroll
        for (int o = 4; o; o >>= 1) {
            s  += __shfl_xor_sync(0xffu, s,  o);
            ss += __shfl_xor_sync(0xffu, ss, o);
        }
        if (threadIdx.x == 0) {
            float mu  = s * (1.0f / HW);
            float var = ss * (1.0f / HW) - mu * mu;
            g_mean[plane] = mu;
            g_rstd[plane] = rsqrtf(var + EPSV);
        }
    }
}

// ---------------------------------------------------------------------------
// Kernel 2: normalize + transpose NCHW -> NHWC, emit bf16 hi/lo
// ---------------------------------------------------------------------------
__global__ void ln_norm_t_kernel(const float* __restrict__ x) {
    __shared__ float t[32][33];
    int b   = blockIdx.z;
    int c0  = blockIdx.y * 32;
    int hw0 = blockIdx.x * 32;
    int plane = b * Cc + c0 + threadIdx.y;
    float v = x[(size_t)plane * HW + hw0 + threadIdx.x];
    v = (v - g_mean[plane]) * g_rstd[plane];
    t[threadIdx.y][threadIdx.x] = v;
    __syncthreads();
    float o = t[threadIdx.x][threadIdx.y];
    size_t idx = ((size_t)(b * HW + hw0 + threadIdx.y)) * Cc + c0 + threadIdx.x;
    __nv_bfloat16 h = __float2bfloat16(o);
    g_a_hi[idx] = h;
    g_a_lo[idx] = __float2bfloat16(o - __bfloat162float(h));
}

// ---------------------------------------------------------------------------
// Kernel 3: weight hi/lo conversion
// ---------------------------------------------------------------------------
__global__ void wconv_kernel(const float* __restrict__ Wq, const float* __restrict__ Wk,
                             const float* __restrict__ Wv, const float* __restrict__ Wo) {
    int idx = blockIdx.x * 256 + threadIdx.x;
    int sel = idx >> 16, off = idx & 65535;
    const float* W = (sel == 0) ? Wq : (sel == 1) ? Wk : (sel == 2) ? Wv : Wo;
    float v = W[off];
    __nv_bfloat16 h = __float2bfloat16(v);
    g_w_hi[idx] = h;
    g_w_lo[idx] = __float2bfloat16(v - __bfloat162float(h));
}

// ---------------------------------------------------------------------------
// Pipelined WMMA GEMM core — term-major MMA order (8 independent acc chains
// per sweep) to cover HMMA latency.
// C[128x128] = Ah*Bh^T + Ah*Bl^T + Al*Bh^T over K=256, 8 chunks of 32.
// ---------------------------------------------------------------------------
#define LDS_ELT 40
#define T_BYTES (128 * LDS_ELT * 2)    // 10240
#define STG_BYTES (4 * T_BYTES)        // 40960
#define LDC 132
#define SM_BYTES (2 * STG_BYTES)       // 81920

__device__ __forceinline__ void gemm_core(
    const __nv_bfloat16* __restrict__ Ah, const __nv_bfloat16* __restrict__ Al,
    const __nv_bfloat16* __restrict__ Wh, const __nv_bfloat16* __restrict__ Wl,
    int m0, int n0, char* smem)
{
    const uint32_t sb = smem_u32(smem);
    const int tid = threadIdx.x;
    const int wid = tid >> 5;
    const int wm = wid & 3;
    const int wn = wid >> 2;

    const char* srcs[4] = {
        (const char*)(Ah + (size_t)m0 * Cc),
        (const char*)(Al + (size_t)m0 * Cc),
        (const char*)(Wh + (size_t)n0 * Cc),
        (const char*)(Wl + (size_t)n0 * Cc)
    };

    wmma::fragment<wmma::accumulator, 16, 16, 16, float> acc[2][4];
    #pragma unroll
    for (int i = 0; i < 2; i++)
        #pragma unroll
        for (int j = 0; j < 4; j++) wmma::fill_fragment(acc[i][j], 0.0f);

    auto load_chunk = [&](int ch, int buf) {
        uint32_t sbase = sb + buf * STG_BYTES;
        #pragma unroll
        for (int t = 0; t < 8; t++) {
            int idx  = t * 256 + tid;
            int tile = idx >> 9;
            int pos  = idx & 511;
            int r    = pos >> 2;
            int seg  = pos & 3;
            uint32_t dst = sbase + tile * T_BYTES + r * 80 + seg * 16;
            const char* src = srcs[tile] + (size_t)r * 512 + ch * 64 + seg * 16;
            cp16(dst, src);
        }
        CP_COMMIT();
    };

    load_chunk(0, 0);

    for (int ch = 0; ch < 8; ch++) {
        if (ch < 7) { load_chunk(ch + 1, (ch + 1) & 1); CP_WAIT1(); }
        else        { CP_WAIT0(); }
        __syncthreads();

        const __nv_bfloat16* Ash = (const __nv_bfloat16*)(smem + (ch & 1) * STG_BYTES);
        const __nv_bfloat16* Asl = (const __nv_bfloat16*)(smem + (ch & 1) * STG_BYTES + T_BYTES);
        const __nv_bfloat16* Bsh = (const __nv_bfloat16*)(smem + (ch & 1) * STG_BYTES + 2 * T_BYTES);
        const __nv_bfloat16* Bsl = (const __nv_bfloat16*)(smem + (ch & 1) * STG_BYTES + 3 * T_BYTES);

        #pragma unroll
        for (int k16 = 0; k16 < 2; k16++) {
            wmma::fragment<wmma::matrix_a, 16, 16, 16, __nv_bfloat16, wmma::row_major> fah[2], fal[2];
            wmma::fragment<wmma::matrix_b, 16, 16, 16, __nv_bfloat16, wmma::col_major> fb[4];

            // --- term HH: Ah * Bh ---
            #pragma unroll
            for (int i = 0; i < 2; i++)
                wmma::load_matrix_sync(fah[i], Ash + (wm * 32 + i * 16) * LDS_ELT + k16 * 16, LDS_ELT);
            #pragma unroll
            for (int j = 0; j < 4; j++)
                wmma::load_matrix_sync(fb[j], Bsh + (wn * 64 + j * 16) * LDS_ELT + k16 * 16, LDS_ELT);
            #pragma unroll
            for (int j = 0; j < 4; j++)
                #pragma unroll
                for (int i = 0; i < 2; i++)
                    wmma::mma_sync(acc[i][j], fah[i], fb[j], acc[i][j]);

            // --- term LH: Al * Bh (fb still holds Bh) ---
            #pragma unroll
            for (int i = 0; i < 2; i++)
                wmma::load_matrix_sync(fal[i], Asl + (wm * 32 + i * 16) * LDS_ELT + k16 * 16, LDS_ELT);
            #pragma unroll
            for (int j = 0; j < 4; j++)
                #pragma unroll
                for (int i = 0; i < 2; i++)
                    wmma::mma_sync(acc[i][j], fal[i], fb[j], acc[i][j]);

            // --- term HL: Ah * Bl (fal dead; fb reloaded with Bl) ---
            #pragma unroll
            for (int j = 0; j < 4; j++)
                wmma::load_matrix_sync(fb[j], Bsl + (wn * 64 + j * 16) * LDS_ELT + k16 * 16, LDS_ELT);
            #pragma unroll
            for (int j = 0; j < 4; j++)
                #pragma unroll
                for (int i = 0; i < 2; i++)
                    wmma::mma_sync(acc[i][j], fah[i], fb[j], acc[i][j]);
        }
        __syncthreads();
    }

    float* Cs = (float*)smem;
    #pragma unroll
    for (int i = 0; i < 2; i++)
        #pragma unroll
        for (int j = 0; j < 4; j++)
            wmma::store_matrix_sync(Cs + (wm * 32 + i * 16) * LDC + wn * 64 + j * 16,
                                    acc[i][j], LDC, wmma::mem_row_major);
    __syncthreads();
}

// ---------------------------------------------------------------------------
// Kernel 4: fused QKV GEMM. grid (NP/128, 2, 3)
// ---------------------------------------------------------------------------
__global__ void __launch_bounds__(256, 2) gemm_qkv_mma(
    const float* __restrict__ bq, const float* __restrict__ bk, const float* __restrict__ bv)
{
    extern __shared__ char smem[];
    const int m0 = blockIdx.x * 128;
    const int n0 = blockIdx.y * 128;
    const int sel = blockIdx.z;

    gemm_core(g_a_hi, g_a_lo,
              g_w_hi + (size_t)sel * 65536, g_w_lo + (size_t)sel * 65536,
              m0, n0, smem);

    const float* bias = (sel == 0) ? bq : (sel == 1) ? bk : bv;
    float* out        = (sel == 0) ? g_q : (sel == 1) ? g_k : g_v;
    const float scale = (sel == 0) ? QSCALE : 1.0f;
    float* Cs = (float*)smem;

    int half = threadIdx.x & 1, mrow = threadIdx.x >> 1;
    float* op = out + (size_t)(m0 + mrow) * Cc + n0;
    #pragma unroll
    for (int j = 0; j < 16; j++) {
        int n = half * 64 + j * 4;
        float4 v;
        v.x = (Cs[mrow * LDC + n + 0] + __ldg(bias + n0 + n + 0)) * scale;
        v.y = (Cs[mrow * LDC + n + 1] + __ldg(bias + n0 + n + 1)) * scale;
        v.z = (Cs[mrow * LDC + n + 2] + __ldg(bias + n0 + n + 2)) * scale;
        v.w = (Cs[mrow * LDC + n + 3] + __ldg(bias + n0 + n + 3)) * scale;
        *(float4*)(op + n) = v;
    }
}

// ---------------------------------------------------------------------------
// Kernel 5: 3x3 neighborhood attention
// ---------------------------------------------------------------------------
__global__ void __launch_bounds__(256) attn_kernel(
    const float* __restrict__ bk, const float* __restrict__ bv)
{
    int warp = (blockIdx.x * blockDim.x + threadIdx.x) >> 5;
    int lane = threadIdx.x & 31;
    if (warp >= NP) return;
    int b  = warp >> 12;
    int hw = warp & 4095;
    int h = hw >> 6, w = hw & 63;
    int co = lane * 8;

    const float* qp = g_q + (size_t)warp * Cc;
    float4 q0 = *(const float4*)(qp + co);
    float4 q1 = *(const float4*)(qp + co + 4);

    float logits[9];
    #pragma unroll
    for (int n = 0; n < 9; n++) {
        int dh = n / 3 - 1, dw = n % 3 - 1;
        int hh = h + dh, ww = w + dw;
        bool ok = (hh >= 0) & (hh < Hh) & (ww >= 0) & (ww < Ww);
        const float* kp = ok ? (g_k + (size_t)((b << 12) + (hh << 6) + ww) * Cc) : bk;
        float4 k0 = *(const float4*)(kp + co);
        float4 k1 = *(const float4*)(kp + co + 4);
        float d = q0.x*k0.x + q0.y*k0.y + q0.z*k0.z + q0.w*k0.w
                + q1.x*k1.x + q1.y*k1.y + q1.z*k1.z + q1.w*k1.w;
        #pragma unroll
        for (int o = 16; o; o >>= 1) d += __shfl_xor_sync(0xffffffffu, d, o);
        logits[n] = d;
    }

    float mx = logits[0];
    #pragma unroll
    for (int n = 1; n < 9; n++) mx = fmaxf(mx, logits[n]);
    float e[9]; float sum = 0.f;
    #pragma unroll
    for (int n = 0; n < 9; n++) { e[n] = __expf(logits[n] - mx); sum += e[n]; }
    float inv = 1.0f / sum;

    float acc[8] = {0,0,0,0,0,0,0,0};
    #pragma unroll
    for (int n = 0; n < 9; n++) {
        int dh = n / 3 - 1, dw = n % 3 - 1;
        int hh = h + dh, ww = w + dw;
        bool ok = (hh >= 0) & (hh < Hh) & (ww >= 0) & (ww < Ww);
        const float* vp = ok ? (g_v + (size_t)((b << 12) + (hh << 6) + ww) * Cc) : bv;
        float a = e[n] * inv;
        float4 v0 = *(const float4*)(vp + co);
        float4 v1 = *(const float4*)(vp + co + 4);
        acc[0] = fmaf(a, v0.x, acc[0]); acc[1] = fmaf(a, v0.y, acc[1]);
        acc[2] = fmaf(a, v0.z, acc[2]); acc[3] = fmaf(a, v0.w, acc[3]);
        acc[4] = fmaf(a, v1.x, acc[4]); acc[5] = fmaf(a, v1.y, acc[5]);
        acc[6] = fmaf(a, v1.z, acc[6]); acc[7] = fmaf(a, v1.w, acc[7]);
    }

    uint32_t ph[4], pl[4];
    #pragma unroll
    for (int i = 0; i < 4; i++) {
        float a0 = acc[2*i], a1 = acc[2*i+1];
        __nv_bfloat162 h2 = __floats2bfloat162_rn(a0, a1);
        float h0 = __low2float(h2), h1 = __high2float(h2);
        __nv_bfloat162 l2 = __floats2bfloat162_rn(a0 - h0, a1 - h1);
        ph[i] = *reinterpret_cast<uint32_t*>(&h2);
        pl[i] = *reinterpret_cast<uint32_t*>(&l2);
    }
    size_t base = (size_t)warp * Cc + co;
    *(uint4*)(g_c_hi + base) = make_uint4(ph[0], ph[1], ph[2], ph[3]);
    *(uint4*)(g_c_lo + base) = make_uint4(pl[0], pl[1], pl[2], pl[3]);
}

// ---------------------------------------------------------------------------
// Kernel 6: output projection GEMM, writes NCHW directly. grid (NP/128, 2)
// ---------------------------------------------------------------------------
__global__ void __launch_bounds__(256, 2) gemm_o_mma(
    const float* __restrict__ bo, float* __restrict__ out)
{
    extern __shared__ char smem[];
    const int m0 = blockIdx.x * 128;
    const int n0 = blockIdx.y * 128;

    gemm_core(g_c_hi, g_c_lo,
              g_w_hi + (size_t)3 * 65536, g_w_lo + (size_t)3 * 65536,
              m0, n0, smem);

    float* Cs = (float*)smem;
    const int wid = threadIdx.x >> 5, lane = threadIdx.x & 31;
    const int b   = m0 >> 12;
    const int hw0 = m0 & 4095;

    for (int nn = wid; nn < 128; nn += 8) {
        int m = lane * 4;
        float bias = __ldg(bo + n0 + nn);
        float4 v;
        v.x = Cs[(m + 0) * LDC + nn] + bias;
        v.y = Cs[(m + 1) * LDC + nn] + bias;
        v.z = Cs[(m + 2) * LDC + nn] + bias;
        v.w = Cs[(m + 3) * LDC + nn] + bias;
        *(float4*)(out + ((size_t)(b * 256 + n0 + nn)) * HW + hw0 + m) = v;
    }
}

// ---------------------------------------------------------------------------
extern "C" void kernel_launch(void* const* d_in, const int* in_sizes, int n_in,
                              void* d_out, int out_size) {
    const float* x  = (const float*)d_in[0];
    const float* Wq = (const float*)d_in[1];
    const float* bq = (const float*)d_in[2];
    const float* Wk = (const float*)d_in[3];
    const float* bk = (const float*)d_in[4];
    const float* Wv = (const float*)d_in[5];
    const float* bv = (const float*)d_in[6];
    const float* Wo = (const float*)d_in[7];
    const float* bo = (const float*)d_in[8];
    float* out = (float*)d_out;

    static int configured = 0;
    if (!configured) {
        cudaFuncSetAttribute(gemm_qkv_mma, cudaFuncAttributeMaxDynamicSharedMemorySize, SM_BYTES);
        cudaFuncSetAttribute(gemm_o_mma,   cudaFuncAttributeMaxDynamicSharedMemorySize, SM_BYTES);
        configured = 1;
    }

    ln_stats_kernel<<<Bn * Cc, 256>>>(x);
    ln_norm_t_kernel<<<dim3(HW / 32, Cc / 32, Bn), dim3(32, 32)>>>(x);
    wconv_kernel<<<(4 * Cc * Cc) / 256, 256>>>(Wq, Wk, Wv, Wo);
    gemm_qkv_mma<<<dim3(NP / 128, 2, 3), 256, SM_BYTES>>>(bq, bk, bv);
    attn_kernel<<<NP / 8, 256>>>(bk, bv);
    gemm_o_mma<<<dim3(NP / 128, 2), 256, SM_BYTES>>>(bo, out);
}

// round 10
// speedup vs baseline: 1.1699x; 1.1699x over previous
#include <cuda_runtime.h>
#include <cuda_bf16.h>
#include <cuda_fp16.h>
#include <mma.h>
#include <cstdint>

using namespace nvcuda;

#define Bn   4
#define Cc   256
#define Hh   64
#define Ww   64
#define HW   4096
#define NP   16384
#define EPSV 1e-5f
#define QSCALE 0.0625f

// ---------------------------------------------------------------------------
// Scratch
// ---------------------------------------------------------------------------
__device__ float g_q[NP * Cc];
__device__ float g_k[NP * Cc];
__device__ float g_v[NP * Cc];
__device__ __half g_a_hf[NP * Cc];             // normalized input NHWC, fp16 hi
__device__ __half g_a_lf[NP * Cc];             // fp16 lo residual
__device__ __nv_bfloat16 g_c_hi[NP * Cc];      // attention ctx bf16 hi
__device__ __nv_bfloat16 g_c_lo[NP * Cc];      // ctx bf16 lo
__device__ __half g_wqkv[3 * Cc * Cc];         // Wq,Wk,Wv fp16 (single)
__device__ __nv_bfloat16 g_wo_hi[Cc * Cc];     // Wo bf16 hi
__device__ __nv_bfloat16 g_wo_lo[Cc * Cc];     // Wo bf16 lo
__device__ float g_mean[Bn * Cc];
__device__ float g_rstd[Bn * Cc];

// ---------------------------------------------------------------------------
__device__ __forceinline__ uint32_t smem_u32(const void* p) {
    uint32_t a;
    asm("{ .reg .u64 t; cvta.to.shared.u64 t, %1; cvt.u32.u64 %0, t; }" : "=r"(a) : "l"(p));
    return a;
}
__device__ __forceinline__ void cp16(uint32_t dst, const void* src) {
    asm volatile("cp.async.ca.shared.global [%0], [%1], 16;" :: "r"(dst), "l"(src));
}
#define CP_COMMIT() asm volatile("cp.async.commit_group;" ::: "memory")
#define CP_WAIT1()  asm volatile("cp.async.wait_group 1;" ::: "memory")
#define CP_WAIT0()  asm volatile("cp.async.wait_group 0;" ::: "memory")

// ---------------------------------------------------------------------------
// Kernel 1: per-(b,c)-plane mean / rstd
// ---------------------------------------------------------------------------
__global__ void ln_stats_kernel(const float* __restrict__ x) {
    int plane = blockIdx.x;
    const float* p = x + (size_t)plane * HW;
    float s = 0.f, ss = 0.f;
    for (int i = threadIdx.x; i < HW; i += 256) {
        float v = p[i];
        s += v; ss += v * v;
    }
    #pragma unroll
    for (int o = 16; o; o >>= 1) {
        s  += __shfl_xor_sync(0xffffffffu, s,  o);
        ss += __shfl_xor_sync(0xffffffffu, ss, o);
    }
    __shared__ float sh1[8], sh2[8];
    int wid = threadIdx.x >> 5, ln = threadIdx.x & 31;
    if (ln == 0) { sh1[wid] = s; sh2[wid] = ss; }
    __syncthreads();
    if (threadIdx.x < 8) {
        s = sh1[threadIdx.x]; ss = sh2[threadIdx.x];
        #pragma unroll
        for (int o = 4; o; o >>= 1) {
            s  += __shfl_xor_sync(0xffu, s,  o);
            ss += __shfl_xor_sync(0xffu, ss, o);
        }
        if (threadIdx.x == 0) {
            float mu  = s * (1.0f / HW);
            float var = ss * (1.0f / HW) - mu * mu;
            g_mean[plane] = mu;
            g_rstd[plane] = rsqrtf(var + EPSV);
        }
    }
}

// ---------------------------------------------------------------------------
// Kernel 2: normalize + transpose NCHW -> NHWC, emit fp16 hi/lo
// ---------------------------------------------------------------------------
__global__ void ln_norm_t_kernel(const float* __restrict__ x) {
    __shared__ float t[32][33];
    int b   = blockIdx.z;
    int c0  = blockIdx.y * 32;
    int hw0 = blockIdx.x * 32;
    int plane = b * Cc + c0 + threadIdx.y;
    float v = x[(size_t)plane * HW + hw0 + threadIdx.x];
    v = (v - g_mean[plane]) * g_rstd[plane];
    t[threadIdx.y][threadIdx.x] = v;
    __syncthreads();
    float o = t[threadIdx.x][threadIdx.y];
    size_t idx = ((size_t)(b * HW + hw0 + threadIdx.y)) * Cc + c0 + threadIdx.x;
    __half h = __float2half_rn(o);
    g_a_hf[idx] = h;
    g_a_lf[idx] = __float2half_rn(o - __half2float(h));
}

// ---------------------------------------------------------------------------
// Kernel 3: weight conversion. Wq,Wk,Wv -> fp16; Wo -> bf16 hi/lo
// ---------------------------------------------------------------------------
__global__ void wconv_kernel(const float* __restrict__ Wq, const float* __restrict__ Wk,
                             const float* __restrict__ Wv, const float* __restrict__ Wo) {
    int idx = blockIdx.x * 256 + threadIdx.x;
    int sel = idx >> 16, off = idx & 65535;
    if (sel < 3) {
        const float* W = (sel == 0) ? Wq : (sel == 1) ? Wk : Wv;
        g_wqkv[idx] = __float2half_rn(W[off]);
    } else {
        float v = Wo[off];
        __nv_bfloat16 h = __float2bfloat16(v);
        g_wo_hi[off] = h;
        g_wo_lo[off] = __float2bfloat16(v - __bfloat162float(h));
    }
}

// ===========================================================================
// fp16 2-term GEMM core (QKV): C[128x128] = (Ah+Al) * Bh^T over K=256.
// 3-stage cp.async pipeline, one syncthreads per chunk.
// ===========================================================================
#define LDS_ELT 40
#define T_BYTES (128 * LDS_ELT * 2)        // 10240
#define STG2 (3 * T_BYTES)                 // 30720 per stage (Ah, Al, Bh)
#define LDC 132
#define SM2_BYTES (3 * STG2)               // 92160; Cs (67584) overlays

__device__ __forceinline__ void gemm_core_f16(
    const __half* __restrict__ Ah, const __half* __restrict__ Al,
    const __half* __restrict__ W, int m0, int n0, char* smem)
{
    const uint32_t sb = smem_u32(smem);
    const int tid = threadIdx.x;
    const int wid = tid >> 5;
    const int wm = wid & 3;
    const int wn = wid >> 2;

    const char* srcs[3] = {
        (const char*)(Ah + (size_t)m0 * Cc),
        (const char*)(Al + (size_t)m0 * Cc),
        (const char*)(W  + (size_t)n0 * Cc)
    };

    wmma::fragment<wmma::accumulator, 16, 16, 16, float> acc[2][4];
    #pragma unroll
    for (int i = 0; i < 2; i++)
        #pragma unroll
        for (int j = 0; j < 4; j++) wmma::fill_fragment(acc[i][j], 0.0f);

    auto load_chunk = [&](int ch, int buf) {
        uint32_t sbase = sb + buf * STG2;
        #pragma unroll
        for (int t = 0; t < 6; t++) {
            int idx  = t * 256 + tid;          // 0..1535
            int row  = idx >> 2;               // 0..383
            int seg  = idx & 3;
            int tile = row >> 7;               // 0..2
            int r    = row & 127;
            uint32_t dst = sbase + tile * T_BYTES + r * 80 + seg * 16;
            const char* src = srcs[tile] + (size_t)r * 512 + ch * 64 + seg * 16;
            cp16(dst, src);
        }
        CP_COMMIT();
    };

    load_chunk(0, 0);
    load_chunk(1, 1);

    for (int ch = 0; ch < 8; ch++) {
        if (ch < 7) CP_WAIT1(); else CP_WAIT0();
        __syncthreads();
        if (ch < 6) load_chunk(ch + 2, (ch + 2) % 3);

        const char* stg = smem + (ch % 3) * STG2;
        const __half* Ash = (const __half*)stg;
        const __half* Asl = (const __half*)(stg + T_BYTES);
        const __half* Bsh = (const __half*)(stg + 2 * T_BYTES);

        #pragma unroll
        for (int k16 = 0; k16 < 2; k16++) {
            wmma::fragment<wmma::matrix_a, 16, 16, 16, __half, wmma::row_major> fah[2], fal[2];
            wmma::fragment<wmma::matrix_b, 16, 16, 16, __half, wmma::col_major> fb[4];
            #pragma unroll
            for (int i = 0; i < 2; i++)
                wmma::load_matrix_sync(fah[i], Ash + (wm * 32 + i * 16) * LDS_ELT + k16 * 16, LDS_ELT);
            #pragma unroll
            for (int j = 0; j < 4; j++)
                wmma::load_matrix_sync(fb[j], Bsh + (wn * 64 + j * 16) * LDS_ELT + k16 * 16, LDS_ELT);
            #pragma unroll
            for (int j = 0; j < 4; j++)
                #pragma unroll
                for (int i = 0; i < 2; i++)
                    wmma::mma_sync(acc[i][j], fah[i], fb[j], acc[i][j]);
            #pragma unroll
            for (int i = 0; i < 2; i++)
                wmma::load_matrix_sync(fal[i], Asl + (wm * 32 + i * 16) * LDS_ELT + k16 * 16, LDS_ELT);
            #pragma unroll
            for (int j = 0; j < 4; j++)
                #pragma unroll
                for (int i = 0; i < 2; i++)
                    wmma::mma_sync(acc[i][j], fal[i], fb[j], acc[i][j]);
        }
    }
    __syncthreads();

    float* Cs = (float*)smem;
    #pragma unroll
    for (int i = 0; i < 2; i++)
        #pragma unroll
        for (int j = 0; j < 4; j++)
            wmma::store_matrix_sync(Cs + (wm * 32 + i * 16) * LDC + wn * 64 + j * 16,
                                    acc[i][j], LDC, wmma::mem_row_major);
    __syncthreads();
}

// ===========================================================================
// bf16 3-term GEMM core (O-proj): C = Ah*Bh + Ah*Bl + Al*Bh.  2-stage.
// ===========================================================================
#define STG3 (4 * T_BYTES)                 // 40960 (Ah, Al, Bh, Bl)
#define SM3_BYTES (2 * STG3)               // 81920

__device__ __forceinline__ void gemm_core_bf16(
    const __nv_bfloat16* __restrict__ Ah, const __nv_bfloat16* __restrict__ Al,
    const __nv_bfloat16* __restrict__ Wh, const __nv_bfloat16* __restrict__ Wl,
    int m0, int n0, char* smem)
{
    const uint32_t sb = smem_u32(smem);
    const int tid = threadIdx.x;
    const int wid = tid >> 5;
    const int wm = wid & 3;
    const int wn = wid >> 2;

    const char* srcs[4] = {
        (const char*)(Ah + (size_t)m0 * Cc),
        (const char*)(Al + (size_t)m0 * Cc),
        (const char*)(Wh + (size_t)n0 * Cc),
        (const char*)(Wl + (size_t)n0 * Cc)
    };

    wmma::fragment<wmma::accumulator, 16, 16, 16, float> acc[2][4];
    #pragma unroll
    for (int i = 0; i < 2; i++)
        #pragma unroll
        for (int j = 0; j < 4; j++) wmma::fill_fragment(acc[i][j], 0.0f);

    auto load_chunk = [&](int ch, int buf) {
        uint32_t sbase = sb + buf * STG3;
        #pragma unroll
        for (int t = 0; t < 8; t++) {
            int idx  = t * 256 + tid;
            int tile = idx >> 9;
            int pos  = idx & 511;
            int r    = pos >> 2;
            int seg  = pos & 3;
            uint32_t dst = sbase + tile * T_BYTES + r * 80 + seg * 16;
            const char* src = srcs[tile] + (size_t)r * 512 + ch * 64 + seg * 16;
            cp16(dst, src);
        }
        CP_COMMIT();
    };

    load_chunk(0, 0);

    for (int ch = 0; ch < 8; ch++) {
        if (ch < 7) { load_chunk(ch + 1, (ch + 1) & 1); CP_WAIT1(); }
        else        { CP_WAIT0(); }
        __syncthreads();

        const char* stg = smem + (ch & 1) * STG3;
        const __nv_bfloat16* Ash = (const __nv_bfloat16*)stg;
        const __nv_bfloat16* Asl = (const __nv_bfloat16*)(stg + T_BYTES);
        const __nv_bfloat16* Bsh = (const __nv_bfloat16*)(stg + 2 * T_BYTES);
        const __nv_bfloat16* Bsl = (const __nv_bfloat16*)(stg + 3 * T_BYTES);

        #pragma unroll
        for (int k16 = 0; k16 < 2; k16++) {
            wmma::fragment<wmma::matrix_a, 16, 16, 16, __nv_bfloat16, wmma::row_major> fah[2], fal[2];
            wmma::fragment<wmma::matrix_b, 16, 16, 16, __nv_bfloat16, wmma::col_major> fb[4];
            #pragma unroll
            for (int i = 0; i < 2; i++)
                wmma::load_matrix_sync(fah[i], Ash + (wm * 32 + i * 16) * LDS_ELT + k16 * 16, LDS_ELT);
            #pragma unroll
            for (int j = 0; j < 4; j++)
                wmma::load_matrix_sync(fb[j], Bsh + (wn * 64 + j * 16) * LDS_ELT + k16 * 16, LDS_ELT);
            #pragma unroll
            for (int j = 0; j < 4; j++)
                #pragma unroll
                for (int i = 0; i < 2; i++)
                    wmma::mma_sync(acc[i][j], fah[i], fb[j], acc[i][j]);
            #pragma unroll
            for (int i = 0; i < 2; i++)
                wmma::load_matrix_sync(fal[i], Asl + (wm * 32 + i * 16) * LDS_ELT + k16 * 16, LDS_ELT);
            #pragma unroll
            for (int j = 0; j < 4; j++)
                #pragma unroll
                for (int i = 0; i < 2; i++)
                    wmma::mma_sync(acc[i][j], fal[i], fb[j], acc[i][j]);
            #pragma unroll
            for (int j = 0; j < 4; j++)
                wmma::load_matrix_sync(fb[j], Bsl + (wn * 64 + j * 16) * LDS_ELT + k16 * 16, LDS_ELT);
            #pragma unroll
            for (int j = 0; j < 4; j++)
                #pragma unroll
                for (int i = 0; i < 2; i++)
                    wmma::mma_sync(acc[i][j], fah[i], fb[j], acc[i][j]);
        }
        __syncthreads();
    }

    float* Cs = (float*)smem;
    #pragma unroll
    for (int i = 0; i < 2; i++)
        #pragma unroll
        for (int j = 0; j < 4; j++)
            wmma::store_matrix_sync(Cs + (wm * 32 + i * 16) * LDC + wn * 64 + j * 16,
                                    acc[i][j], LDC, wmma::mem_row_major);
    __syncthreads();
}

// ---------------------------------------------------------------------------
// Kernel 4: fused QKV GEMM (fp16 2-term). grid (NP/128, 2, 3)
// ---------------------------------------------------------------------------
__global__ void __launch_bounds__(256, 2) gemm_qkv_mma(
    const float* __restrict__ bq, const float* __restrict__ bk, const float* __restrict__ bv)
{
    extern __shared__ char smem[];
    const int m0 = blockIdx.x * 128;
    const int n0 = blockIdx.y * 128;
    const int sel = blockIdx.z;

    gemm_core_f16(g_a_hf, g_a_lf, g_wqkv + (size_t)sel * 65536, m0, n0, smem);

    const float* bias = (sel == 0) ? bq : (sel == 1) ? bk : bv;
    float* out        = (sel == 0) ? g_q : (sel == 1) ? g_k : g_v;
    const float scale = (sel == 0) ? QSCALE : 1.0f;
    float* Cs = (float*)smem;

    int half = threadIdx.x & 1, mrow = threadIdx.x >> 1;
    float* op = out + (size_t)(m0 + mrow) * Cc + n0;
    #pragma unroll
    for (int j = 0; j < 16; j++) {
        int n = half * 64 + j * 4;
        float4 v;
        v.x = (Cs[mrow * LDC + n + 0] + __ldg(bias + n0 + n + 0)) * scale;
        v.y = (Cs[mrow * LDC + n + 1] + __ldg(bias + n0 + n + 1)) * scale;
        v.z = (Cs[mrow * LDC + n + 2] + __ldg(bias + n0 + n + 2)) * scale;
        v.w = (Cs[mrow * LDC + n + 3] + __ldg(bias + n0 + n + 3)) * scale;
        *(float4*)(op + n) = v;
    }
}

// ---------------------------------------------------------------------------
// Kernel 5: 3x3 neighborhood attention (bf16 hi/lo ctx out)
// ---------------------------------------------------------------------------
__global__ void __launch_bounds__(256) attn_kernel(
    const float* __restrict__ bk, const float* __restrict__ bv)
{
    int warp = (blockIdx.x * blockDim.x + threadIdx.x) >> 5;
    int lane = threadIdx.x & 31;
    if (warp >= NP) return;
    int b  = warp >> 12;
    int hw = warp & 4095;
    int h = hw >> 6, w = hw & 63;
    int co = lane * 8;

    const float* qp = g_q + (size_t)warp * Cc;
    float4 q0 = *(const float4*)(qp + co);
    float4 q1 = *(const float4*)(qp + co + 4);

    float logits[9];
    #pragma unroll
    for (int n = 0; n < 9; n++) {
        int dh = n / 3 - 1, dw = n % 3 - 1;
        int hh = h + dh, ww = w + dw;
        bool ok = (hh >= 0) & (hh < Hh) & (ww >= 0) & (ww < Ww);
        const float* kp = ok ? (g_k + (size_t)((b << 12) + (hh << 6) + ww) * Cc) : bk;
        float4 k0 = *(const float4*)(kp + co);
        float4 k1 = *(const float4*)(kp + co + 4);
        float d = q0.x*k0.x + q0.y*k0.y + q0.z*k0.z + q0.w*k0.w
                + q1.x*k1.x + q1.y*k1.y + q1.z*k1.z + q1.w*k1.w;
        #pragma unroll
        for (int o = 16; o; o >>= 1) d += __shfl_xor_sync(0xffffffffu, d, o);
        logits[n] = d;
    }

    float mx = logits[0];
    #pragma unroll
    for (int n = 1; n < 9; n++) mx = fmaxf(mx, logits[n]);
    float e[9]; float sum = 0.f;
    #pragma unroll
    for (int n = 0; n < 9; n++) { e[n] = __expf(logits[n] - mx); sum += e[n]; }
    float inv = 1.0f / sum;

    float acc[8] = {0,0,0,0,0,0,0,0};
    #pragma unroll
    for (int n = 0; n < 9; n++) {
        int dh = n / 3 - 1, dw = n % 3 - 1;
        int hh = h + dh, ww = w + dw;
        bool ok = (hh >= 0) & (hh < Hh) & (ww >= 0) & (ww < Ww);
        const float* vp = ok ? (g_v + (size_t)((b << 12) + (hh << 6) + ww) * Cc) : bv;
        float a = e[n] * inv;
        float4 v0 = *(const float4*)(vp + co);
        float4 v1 = *(const float4*)(vp + co + 4);
        acc[0] = fmaf(a, v0.x, acc[0]); acc[1] = fmaf(a, v0.y, acc[1]);
        acc[2] = fmaf(a, v0.z, acc[2]); acc[3] = fmaf(a, v0.w, acc[3]);
        acc[4] = fmaf(a, v1.x, acc[4]); acc[5] = fmaf(a, v1.y, acc[5]);
        acc[6] = fmaf(a, v1.z, acc[6]); acc[7] = fmaf(a, v1.w, acc[7]);
    }

    uint32_t ph[4], pl[4];
    #pragma unroll
    for (int i = 0; i < 4; i++) {
        float a0 = acc[2*i], a1 = acc[2*i+1];
        __nv_bfloat162 h2 = __floats2bfloat162_rn(a0, a1);
        float h0 = __low2float(h2), h1 = __high2float(h2);
        __nv_bfloat162 l2 = __floats2bfloat162_rn(a0 - h0, a1 - h1);
        ph[i] = *reinterpret_cast<uint32_t*>(&h2);
        pl[i] = *reinterpret_cast<uint32_t*>(&l2);
    }
    size_t base = (size_t)warp * Cc + co;
    *(uint4*)(g_c_hi + base) = make_uint4(ph[0], ph[1], ph[2], ph[3]);
    *(uint4*)(g_c_lo + base) = make_uint4(pl[0], pl[1], pl[2], pl[3]);
}

// ---------------------------------------------------------------------------
// Kernel 6: output projection GEMM (bf16 3-term), writes NCHW. grid (NP/128, 2)
// ---------------------------------------------------------------------------
__global__ void __launch_bounds__(256, 2) gemm_o_mma(
    const float* __restrict__ bo, float* __restrict__ out)
{
    extern __shared__ char smem[];
    const int m0 = blockIdx.x * 128;
    const int n0 = blockIdx.y * 128;

    gemm_core_bf16(g_c_hi, g_c_lo, g_wo_hi, g_wo_lo, m0, n0, smem);

    float* Cs = (float*)smem;
    const int wid = threadIdx.x >> 5, lane = threadIdx.x & 31;
    const int b   = m0 >> 12;
    const int hw0 = m0 & 4095;

    for (int nn = wid; nn < 128; nn += 8) {
        int m = lane * 4;
        float bias = __ldg(bo + n0 + nn);
        float4 v;
        v.x = Cs[(m + 0) * LDC + nn] + bias;
        v.y = Cs[(m + 1) * LDC + nn] + bias;
        v.z = Cs[(m + 2) * LDC + nn] + bias;
        v.w = Cs[(m + 3) * LDC + nn] + bias;
        *(float4*)(out + ((size_t)(b * 256 + n0 + nn)) * HW + hw0 + m) = v;
    }
}

// ---------------------------------------------------------------------------
extern "C" void kernel_launch(void* const* d_in, const int* in_sizes, int n_in,
                              void* d_out, int out_size) {
    const float* x  = (const float*)d_in[0];
    const float* Wq = (const float*)d_in[1];
    const float* bq = (const float*)d_in[2];
    const float* Wk = (const float*)d_in[3];
    const float* bk = (const float*)d_in[4];
    const float* Wv = (const float*)d_in[5];
    const float* bv = (const float*)d_in[6];
    const float* Wo = (const float*)d_in[7];
    const float* bo = (const float*)d_in[8];
    float* out = (float*)d_out;

    static int configured = 0;
    if (!configured) {
        cudaFuncSetAttribute(gemm_qkv_mma, cudaFuncAttributeMaxDynamicSharedMemorySize, SM2_BYTES);
        cudaFuncSetAttribute(gemm_o_mma,   cudaFuncAttributeMaxDynamicSharedMemorySize, SM3_BYTES);
        configured = 1;
    }

    ln_stats_kernel<<<Bn * Cc, 256>>>(x);
    ln_norm_t_kernel<<<dim3(HW / 32, Cc / 32, Bn), dim3(32, 32)>>>(x);
    wconv_kernel<<<(4 * Cc * Cc) / 256, 256>>>(Wq, Wk, Wv, Wo);
    gemm_qkv_mma<<<dim3(NP / 128, 2, 3), 256, SM2_BYTES>>>(bq, bk, bv);
    attn_kernel<<<NP / 8, 256>>>(bk, bv);
    gemm_o_mma<<<dim3(NP / 128, 2), 256, SM3_BYTES>>>(bo, out);
}

// round 11
// speedup vs baseline: 1.3266x; 1.1340x over previous
#include <cuda_runtime.h>
#include <cuda_bf16.h>
#include <cuda_fp16.h>
#include <mma.h>
#include <cstdint>

using namespace nvcuda;

#define Bn   4
#define Cc   256
#define Hh   64
#define Ww   64
#define HW   4096
#define NP   16384
#define EPSV 1e-5f
#define QSCALE 0.0625f

// ---------------------------------------------------------------------------
// Scratch
// ---------------------------------------------------------------------------
__device__ float g_q[NP * Cc];
__device__ float g_k[NP * Cc];
__device__ float g_v[NP * Cc];
__device__ __half g_a_hf[NP * Cc];     // normalized input NHWC, fp16 hi
__device__ __half g_a_lf[NP * Cc];     // fp16 lo residual
__device__ __half g_c_hf[NP * Cc];     // attention ctx fp16 hi
__device__ __half g_c_lf[NP * Cc];     // ctx fp16 lo
__device__ __half g_w[4 * Cc * Cc];    // Wq,Wk,Wv,Wo fp16
__device__ float g_mean[Bn * Cc];
__device__ float g_rstd[Bn * Cc];

// ---------------------------------------------------------------------------
__device__ __forceinline__ uint32_t smem_u32(const void* p) {
    uint32_t a;
    asm("{ .reg .u64 t; cvta.to.shared.u64 t, %1; cvt.u32.u64 %0, t; }" : "=r"(a) : "l"(p));
    return a;
}
__device__ __forceinline__ void cp16(uint32_t dst, const void* src) {
    asm volatile("cp.async.ca.shared.global [%0], [%1], 16;" :: "r"(dst), "l"(src));
}
#define CP_COMMIT() asm volatile("cp.async.commit_group;" ::: "memory")
#define CP_WAIT1()  asm volatile("cp.async.wait_group 1;" ::: "memory")
#define CP_WAIT0()  asm volatile("cp.async.wait_group 0;" ::: "memory")

// ---------------------------------------------------------------------------
// Kernel 1: per-(b,c)-plane mean / rstd
// ---------------------------------------------------------------------------
__global__ void ln_stats_kernel(const float* __restrict__ x) {
    int plane = blockIdx.x;
    const float* p = x + (size_t)plane * HW;
    float s = 0.f, ss = 0.f;
    for (int i = threadIdx.x; i < HW; i += 256) {
        float v = p[i];
        s += v; ss += v * v;
    }
    #pragma unroll
    for (int o = 16; o; o >>= 1) {
        s  += __shfl_xor_sync(0xffffffffu, s,  o);
        ss += __shfl_xor_sync(0xffffffffu, ss, o);
    }
    __shared__ float sh1[8], sh2[8];
    int wid = threadIdx.x >> 5, ln = threadIdx.x & 31;
    if (ln == 0) { sh1[wid] = s; sh2[wid] = ss; }
    __syncthreads();
    if (threadIdx.x < 8) {
        s = sh1[threadIdx.x]; ss = sh2[threadIdx.x];
        #pragma unroll
        for (int o = 4; o; o >>= 1) {
            s  += __shfl_xor_sync(0xffu, s,  o);
            ss += __shfl_xor_sync(0xffu, ss, o);
        }
        if (threadIdx.x == 0) {
            float mu  = s * (1.0f / HW);
            float var = ss * (1.0f / HW) - mu * mu;
            g_mean[plane] = mu;
            g_rstd[plane] = rsqrtf(var + EPSV);
        }
    }
}

// ---------------------------------------------------------------------------
// Kernel 2: normalize + transpose NCHW -> NHWC, emit fp16 hi/lo
// ---------------------------------------------------------------------------
__global__ void ln_norm_t_kernel(const float* __restrict__ x) {
    __shared__ float t[32][33];
    int b   = blockIdx.z;
    int c0  = blockIdx.y * 32;
    int hw0 = blockIdx.x * 32;
    int plane = b * Cc + c0 + threadIdx.y;
    float v = x[(size_t)plane * HW + hw0 + threadIdx.x];
    v = (v - g_mean[plane]) * g_rstd[plane];
    t[threadIdx.y][threadIdx.x] = v;
    __syncthreads();
    float o = t[threadIdx.x][threadIdx.y];
    size_t idx = ((size_t)(b * HW + hw0 + threadIdx.y)) * Cc + c0 + threadIdx.x;
    __half h = __float2half_rn(o);
    g_a_hf[idx] = h;
    g_a_lf[idx] = __float2half_rn(o - __half2float(h));
}

// ---------------------------------------------------------------------------
// Kernel 3: weight conversion: all 4 weights -> fp16
// ---------------------------------------------------------------------------
__global__ void wconv_kernel(const float* __restrict__ Wq, const float* __restrict__ Wk,
                             const float* __restrict__ Wv, const float* __restrict__ Wo) {
    int idx = blockIdx.x * 256 + threadIdx.x;
    int sel = idx >> 16, off = idx & 65535;
    const float* W = (sel == 0) ? Wq : (sel == 1) ? Wk : (sel == 2) ? Wv : Wo;
    g_w[idx] = __float2half_rn(W[off]);
}

// ===========================================================================
// fp16 GEMM core, NT terms (1: Ah*B ; 2: (Ah+Al)*B).
// C[128x128] over K=256. 3-stage cp.async pipeline, 1 sync per chunk.
// Result left in smem Cs[128][132] fp32.
// ===========================================================================
#define LDS_ELT 40
#define T_BYTES (128 * LDS_ELT * 2)        // 10240
#define LDC 132
#define SM_NT1 67584                       // max(3*2*10240=61440, Cs 67584)
#define SM_NT2 92160                       // 3*3*10240 (Cs 67584 overlays)

template <int NT>
__device__ __forceinline__ void gemm_core_f16(
    const __half* __restrict__ Ah, const __half* __restrict__ Al,
    const __half* __restrict__ W, int m0, int n0, char* smem)
{
    constexpr int NTILES = NT + 1;
    constexpr int STG = NTILES * T_BYTES;

    const uint32_t sb = smem_u32(smem);
    const int tid = threadIdx.x;
    const int wid = tid >> 5;
    const int wm = wid & 3;
    const int wn = wid >> 2;

    const char* srcs[NTILES];
    srcs[0] = (const char*)(Ah + (size_t)m0 * Cc);
    if (NT == 2) srcs[1] = (const char*)(Al + (size_t)m0 * Cc);
    srcs[NTILES - 1] = (const char*)(W + (size_t)n0 * Cc);

    wmma::fragment<wmma::accumulator, 16, 16, 16, float> acc[2][4];
    #pragma unroll
    for (int i = 0; i < 2; i++)
        #pragma unroll
        for (int j = 0; j < 4; j++) wmma::fill_fragment(acc[i][j], 0.0f);

    auto load_chunk = [&](int ch, int buf) {
        uint32_t sbase = sb + buf * STG;
        #pragma unroll
        for (int t = 0; t < NTILES * 2; t++) {
            int idx  = t * 256 + tid;
            int row  = idx >> 2;
            int seg  = idx & 3;
            int tile = row >> 7;
            int r    = row & 127;
            uint32_t dst = sbase + tile * T_BYTES + r * 80 + seg * 16;
            const char* src = srcs[tile] + (size_t)r * 512 + ch * 64 + seg * 16;
            cp16(dst, src);
        }
        CP_COMMIT();
    };

    load_chunk(0, 0);
    load_chunk(1, 1);

    for (int ch = 0; ch < 8; ch++) {
        if (ch < 7) CP_WAIT1(); else CP_WAIT0();
        __syncthreads();
        if (ch < 6) load_chunk(ch + 2, (ch + 2) % 3);

        const char* stg = smem + (ch % 3) * STG;
        const __half* Ash = (const __half*)stg;
        const __half* Asl = (const __half*)(stg + T_BYTES);
        const __half* Bsh = (const __half*)(stg + (NTILES - 1) * T_BYTES);

        #pragma unroll
        for (int k16 = 0; k16 < 2; k16++) {
            wmma::fragment<wmma::matrix_a, 16, 16, 16, __half, wmma::row_major> fa[2];
            wmma::fragment<wmma::matrix_b, 16, 16, 16, __half, wmma::col_major> fb[4];
            #pragma unroll
            for (int i = 0; i < 2; i++)
                wmma::load_matrix_sync(fa[i], Ash + (wm * 32 + i * 16) * LDS_ELT + k16 * 16, LDS_ELT);
            #pragma unroll
            for (int j = 0; j < 4; j++)
                wmma::load_matrix_sync(fb[j], Bsh + (wn * 64 + j * 16) * LDS_ELT + k16 * 16, LDS_ELT);
            #pragma unroll
            for (int j = 0; j < 4; j++)
                #pragma unroll
                for (int i = 0; i < 2; i++)
                    wmma::mma_sync(acc[i][j], fa[i], fb[j], acc[i][j]);
            if (NT == 2) {
                #pragma unroll
                for (int i = 0; i < 2; i++)
                    wmma::load_matrix_sync(fa[i], Asl + (wm * 32 + i * 16) * LDS_ELT + k16 * 16, LDS_ELT);
                #pragma unroll
                for (int j = 0; j < 4; j++)
                    #pragma unroll
                    for (int i = 0; i < 2; i++)
                        wmma::mma_sync(acc[i][j], fa[i], fb[j], acc[i][j]);
            }
        }
    }
    __syncthreads();

    float* Cs = (float*)smem;
    #pragma unroll
    for (int i = 0; i < 2; i++)
        #pragma unroll
        for (int j = 0; j < 4; j++)
            wmma::store_matrix_sync(Cs + (wm * 32 + i * 16) * LDC + wn * 64 + j * 16,
                                    acc[i][j], LDC, wmma::mem_row_major);
    __syncthreads();
}

// Common NHWC epilogue: Cs + bias (scaled) -> out rows
__device__ __forceinline__ void epilogue_rows(
    char* smem, float* out, const float* bias, int m0, int n0, float scale)
{
    float* Cs = (float*)smem;
    int half = threadIdx.x & 1, mrow = threadIdx.x >> 1;
    float* op = out + (size_t)(m0 + mrow) * Cc + n0;
    #pragma unroll
    for (int j = 0; j < 16; j++) {
        int n = half * 64 + j * 4;
        float4 v;
        v.x = (Cs[mrow * LDC + n + 0] + __ldg(bias + n0 + n + 0)) * scale;
        v.y = (Cs[mrow * LDC + n + 1] + __ldg(bias + n0 + n + 1)) * scale;
        v.z = (Cs[mrow * LDC + n + 2] + __ldg(bias + n0 + n + 2)) * scale;
        v.w = (Cs[mrow * LDC + n + 3] + __ldg(bias + n0 + n + 3)) * scale;
        *(float4*)(op + n) = v;
    }
}

// ---------------------------------------------------------------------------
// Kernel 4a: Q/K GEMM, fp16 1-term. grid (NP/128, 2, 2)
// ---------------------------------------------------------------------------
__global__ void __launch_bounds__(256, 2) gemm_qk_mma(
    const float* __restrict__ bq, const float* __restrict__ bk)
{
    extern __shared__ char smem[];
    const int m0 = blockIdx.x * 128;
    const int n0 = blockIdx.y * 128;
    const int sel = blockIdx.z;                  // 0=Q, 1=K

    gemm_core_f16<1>(g_a_hf, nullptr, g_w + (size_t)sel * 65536, m0, n0, smem);
    epilogue_rows(smem, (sel == 0) ? g_q : g_k, (sel == 0) ? bq : bk,
                  m0, n0, (sel == 0) ? QSCALE : 1.0f);
}

// ---------------------------------------------------------------------------
// Kernel 4b: V GEMM, fp16 2-term. grid (NP/128, 2)
// ---------------------------------------------------------------------------
__global__ void __launch_bounds__(256, 2) gemm_v_mma(const float* __restrict__ bv)
{
    extern __shared__ char smem[];
    const int m0 = blockIdx.x * 128;
    const int n0 = blockIdx.y * 128;
    gemm_core_f16<2>(g_a_hf, g_a_lf, g_w + (size_t)2 * 65536, m0, n0, smem);
    epilogue_rows(smem, g_v, bv, m0, n0, 1.0f);
}

// ---------------------------------------------------------------------------
// Kernel 5: 3x3 neighborhood attention (fp16 hi/lo ctx out)
// ---------------------------------------------------------------------------
__global__ void __launch_bounds__(256) attn_kernel(
    const float* __restrict__ bk, const float* __restrict__ bv)
{
    int warp = (blockIdx.x * blockDim.x + threadIdx.x) >> 5;
    int lane = threadIdx.x & 31;
    if (warp >= NP) return;
    int b  = warp >> 12;
    int hw = warp & 4095;
    int h = hw >> 6, w = hw & 63;
    int co = lane * 8;

    const float* qp = g_q + (size_t)warp * Cc;
    float4 q0 = *(const float4*)(qp + co);
    float4 q1 = *(const float4*)(qp + co + 4);

    float logits[9];
    #pragma unroll
    for (int n = 0; n < 9; n++) {
        int dh = n / 3 - 1, dw = n % 3 - 1;
        int hh = h + dh, ww = w + dw;
        bool ok = (hh >= 0) & (hh < Hh) & (ww >= 0) & (ww < Ww);
        const float* kp = ok ? (g_k + (size_t)((b << 12) + (hh << 6) + ww) * Cc) : bk;
        float4 k0 = *(const float4*)(kp + co);
        float4 k1 = *(const float4*)(kp + co + 4);
        float d = q0.x*k0.x + q0.y*k0.y + q0.z*k0.z + q0.w*k0.w
                + q1.x*k1.x + q1.y*k1.y + q1.z*k1.z + q1.w*k1.w;
        #pragma unroll
        for (int o = 16; o; o >>= 1) d += __shfl_xor_sync(0xffffffffu, d, o);
        logits[n] = d;
    }

    float mx = logits[0];
    #pragma unroll
    for (int n = 1; n < 9; n++) mx = fmaxf(mx, logits[n]);
    float e[9]; float sum = 0.f;
    #pragma unroll
    for (int n = 0; n < 9; n++) { e[n] = __expf(logits[n] - mx); sum += e[n]; }
    float inv = 1.0f / sum;

    float acc[8] = {0,0,0,0,0,0,0,0};
    #pragma unroll
    for (int n = 0; n < 9; n++) {
        int dh = n / 3 - 1, dw = n % 3 - 1;
        int hh = h + dh, ww = w + dw;
        bool ok = (hh >= 0) & (hh < Hh) & (ww >= 0) & (ww < Ww);
        const float* vp = ok ? (g_v + (size_t)((b << 12) + (hh << 6) + ww) * Cc) : bv;
        float a = e[n] * inv;
        float4 v0 = *(const float4*)(vp + co);
        float4 v1 = *(const float4*)(vp + co + 4);
        acc[0] = fmaf(a, v0.x, acc[0]); acc[1] = fmaf(a, v0.y, acc[1]);
        acc[2] = fmaf(a, v0.z, acc[2]); acc[3] = fmaf(a, v0.w, acc[3]);
        acc[4] = fmaf(a, v1.x, acc[4]); acc[5] = fmaf(a, v1.y, acc[5]);
        acc[6] = fmaf(a, v1.z, acc[6]); acc[7] = fmaf(a, v1.w, acc[7]);
    }

    uint32_t ph[4], pl[4];
    #pragma unroll
    for (int i = 0; i < 4; i++) {
        float a0 = acc[2*i], a1 = acc[2*i+1];
        __half h0 = __float2half_rn(a0), h1 = __float2half_rn(a1);
        __half l0 = __float2half_rn(a0 - __half2float(h0));
        __half l1 = __float2half_rn(a1 - __half2float(h1));
        __half2 hp = __halves2half2(h0, h1);
        __half2 lp = __halves2half2(l0, l1);
        ph[i] = *reinterpret_cast<uint32_t*>(&hp);
        pl[i] = *reinterpret_cast<uint32_t*>(&lp);
    }
    size_t base = (size_t)warp * Cc + co;
    *(uint4*)(g_c_hf + base) = make_uint4(ph[0], ph[1], ph[2], ph[3]);
    *(uint4*)(g_c_lf + base) = make_uint4(pl[0], pl[1], pl[2], pl[3]);
}

// ---------------------------------------------------------------------------
// Kernel 6: output projection GEMM (fp16 2-term), writes NCHW. grid (NP/128, 2)
// ---------------------------------------------------------------------------
__global__ void __launch_bounds__(256, 2) gemm_o_mma(
    const float* __restrict__ bo, float* __restrict__ out)
{
    extern __shared__ char smem[];
    const int m0 = blockIdx.x * 128;
    const int n0 = blockIdx.y * 128;

    gemm_core_f16<2>(g_c_hf, g_c_lf, g_w + (size_t)3 * 65536, m0, n0, smem);

    float* Cs = (float*)smem;
    const int wid = threadIdx.x >> 5, lane = threadIdx.x & 31;
    const int b   = m0 >> 12;
    const int hw0 = m0 & 4095;

    for (int nn = wid; nn < 128; nn += 8) {
        int m = lane * 4;
        float bias = __ldg(bo + n0 + nn);
        float4 v;
        v.x = Cs[(m + 0) * LDC + nn] + bias;
        v.y = Cs[(m + 1) * LDC + nn] + bias;
        v.z = Cs[(m + 2) * LDC + nn] + bias;
        v.w = Cs[(m + 3) * LDC + nn] + bias;
        *(float4*)(out + ((size_t)(b * 256 + n0 + nn)) * HW + hw0 + m) = v;
    }
}

// ---------------------------------------------------------------------------
extern "C" void kernel_launch(void* const* d_in, const int* in_sizes, int n_in,
                              void* d_out, int out_size) {
    const float* x  = (const float*)d_in[0];
    const float* Wq = (const float*)d_in[1];
    const float* bq = (const float*)d_in[2];
    const float* Wk = (const float*)d_in[3];
    const float* bk = (const float*)d_in[4];
    const float* Wv = (const float*)d_in[5];
    const float* bv = (const float*)d_in[6];
    const float* Wo = (const float*)d_in[7];
    const float* bo = (const float*)d_in[8];
    float* out = (float*)d_out;

    static int configured = 0;
    if (!configured) {
        cudaFuncSetAttribute(gemm_qk_mma, cudaFuncAttributeMaxDynamicSharedMemorySize, SM_NT1);
        cudaFuncSetAttribute(gemm_v_mma,  cudaFuncAttributeMaxDynamicSharedMemorySize, SM_NT2);
        cudaFuncSetAttribute(gemm_o_mma,  cudaFuncAttributeMaxDynamicSharedMemorySize, SM_NT2);
        configured = 1;
    }

    ln_stats_kernel<<<Bn * Cc, 256>>>(x);
    ln_norm_t_kernel<<<dim3(HW / 32, Cc / 32, Bn), dim3(32, 32)>>>(x);
    wconv_kernel<<<(4 * Cc * Cc) / 256, 256>>>(Wq, Wk, Wv, Wo);
    gemm_qk_mma<<<dim3(NP / 128, 2, 2), 256, SM_NT1>>>(bq, bk);
    gemm_v_mma<<<dim3(NP / 128, 2), 256, SM_NT2>>>(bv);
    attn_kernel<<<NP / 8, 256>>>(bk, bv);
    gemm_o_mma<<<dim3(NP / 128, 2), 256, SM_NT2>>>(bo, out);
}

// round 12
// speedup vs baseline: 1.3939x; 1.0507x over previous
#include <cuda_runtime.h>
#include <cuda_bf16.h>
#include <cuda_fp16.h>
#include <mma.h>
#include <cstdint>

using namespace nvcuda;

#define Bn   4
#define Cc   256
#define Hh   64
#define Ww   64
#define HW   4096
#define NP   16384
#define EPSV 1e-5f
#define QSCALE 0.0625f

// ---------------------------------------------------------------------------
// Scratch
// ---------------------------------------------------------------------------
__device__ __half g_q[NP * Cc];        // Q fp16 (scaled, biased)
__device__ __half g_k[NP * Cc];        // K fp16
__device__ float  g_v[NP * Cc];        // V fp32
__device__ __half g_a_hf[NP * Cc];     // normalized input NHWC, fp16 hi
__device__ __half g_a_lf[NP * Cc];     // fp16 lo residual
__device__ __half g_c_hf[NP * Cc];     // attention ctx fp16 hi
__device__ __half g_c_lf[NP * Cc];     // ctx fp16 lo
__device__ __half g_w[4 * Cc * Cc];    // Wq,Wk,Wv,Wo fp16
__device__ float g_mean[Bn * Cc];
__device__ float g_rstd[Bn * Cc];

// ---------------------------------------------------------------------------
__device__ __forceinline__ uint32_t smem_u32(const void* p) {
    uint32_t a;
    asm("{ .reg .u64 t; cvta.to.shared.u64 t, %1; cvt.u32.u64 %0, t; }" : "=r"(a) : "l"(p));
    return a;
}
__device__ __forceinline__ void cp16(uint32_t dst, const void* src) {
    asm volatile("cp.async.ca.shared.global [%0], [%1], 16;" :: "r"(dst), "l"(src));
}
#define CP_COMMIT() asm volatile("cp.async.commit_group;" ::: "memory")
#define CP_WAIT1()  asm volatile("cp.async.wait_group 1;" ::: "memory")
#define CP_WAIT0()  asm volatile("cp.async.wait_group 0;" ::: "memory")

// ---------------------------------------------------------------------------
// Kernel 1: per-(b,c)-plane mean / rstd
// ---------------------------------------------------------------------------
__global__ void ln_stats_kernel(const float* __restrict__ x) {
    int plane = blockIdx.x;
    const float* p = x + (size_t)plane * HW;
    float s = 0.f, ss = 0.f;
    for (int i = threadIdx.x; i < HW; i += 256) {
        float v = p[i];
        s += v; ss += v * v;
    }
    #pragma unroll
    for (int o = 16; o; o >>= 1) {
        s  += __shfl_xor_sync(0xffffffffu, s,  o);
        ss += __shfl_xor_sync(0xffffffffu, ss, o);
    }
    __shared__ float sh1[8], sh2[8];
    int wid = threadIdx.x >> 5, ln = threadIdx.x & 31;
    if (ln == 0) { sh1[wid] = s; sh2[wid] = ss; }
    __syncthreads();
    if (threadIdx.x < 8) {
        s = sh1[threadIdx.x]; ss = sh2[threadIdx.x];
        #pragma unroll
        for (int o = 4; o; o >>= 1) {
            s  += __shfl_xor_sync(0xffu, s,  o);
            ss += __shfl_xor_sync(0xffu, ss, o);
        }
        if (threadIdx.x == 0) {
            float mu  = s * (1.0f / HW);
            float var = ss * (1.0f / HW) - mu * mu;
            g_mean[plane] = mu;
            g_rstd[plane] = rsqrtf(var + EPSV);
        }
    }
}

// ---------------------------------------------------------------------------
// Kernel 2: normalize + transpose NCHW -> NHWC, emit fp16 hi/lo
// ---------------------------------------------------------------------------
__global__ void ln_norm_t_kernel(const float* __restrict__ x) {
    __shared__ float t[32][33];
    int b   = blockIdx.z;
    int c0  = blockIdx.y * 32;
    int hw0 = blockIdx.x * 32;
    int plane = b * Cc + c0 + threadIdx.y;
    float v = x[(size_t)plane * HW + hw0 + threadIdx.x];
    v = (v - g_mean[plane]) * g_rstd[plane];
    t[threadIdx.y][threadIdx.x] = v;
    __syncthreads();
    float o = t[threadIdx.x][threadIdx.y];
    size_t idx = ((size_t)(b * HW + hw0 + threadIdx.y)) * Cc + c0 + threadIdx.x;
    __half h = __float2half_rn(o);
    g_a_hf[idx] = h;
    g_a_lf[idx] = __float2half_rn(o - __half2float(h));
}

// ---------------------------------------------------------------------------
// Kernel 3: weight conversion: all 4 weights -> fp16
// ---------------------------------------------------------------------------
__global__ void wconv_kernel(const float* __restrict__ Wq, const float* __restrict__ Wk,
                             const float* __restrict__ Wv, const float* __restrict__ Wo) {
    int idx = blockIdx.x * 256 + threadIdx.x;
    int sel = idx >> 16, off = idx & 65535;
    const float* W = (sel == 0) ? Wq : (sel == 1) ? Wk : (sel == 2) ? Wv : Wo;
    g_w[idx] = __float2half_rn(W[off]);
}

// ===========================================================================
// fp16 GEMM core, NT terms (1: Ah*B ; 2: (Ah+Al)*B).
// C[128x128] over K=256 in 4 chunks of K=64. 2-stage cp.async pipeline.
// Result left in smem Cs[128][132] fp32.
// ===========================================================================
#define LDS_ELT 72                         // halves per staged row (64 + 8 pad)
#define T_BYTES (128 * LDS_ELT * 2)        // 18432
#define LDC 132
#define SM_NT1 73728                       // 2 stages * 2 tiles (Cs 67584 overlays)
#define SM_NT2 110592                      // 2 stages * 3 tiles

template <int NT>
__device__ __forceinline__ void gemm_core_f16(
    const __half* __restrict__ Ah, const __half* __restrict__ Al,
    const __half* __restrict__ W, int m0, int n0, char* smem)
{
    constexpr int NTILES = NT + 1;
    constexpr int STG = NTILES * T_BYTES;

    const uint32_t sb = smem_u32(smem);
    const int tid = threadIdx.x;
    const int wid = tid >> 5;
    const int wm = wid & 3;
    const int wn = wid >> 2;

    const char* srcs[NTILES];
    srcs[0] = (const char*)(Ah + (size_t)m0 * Cc);
    if (NT == 2) srcs[1] = (const char*)(Al + (size_t)m0 * Cc);
    srcs[NTILES - 1] = (const char*)(W + (size_t)n0 * Cc);

    wmma::fragment<wmma::accumulator, 16, 16, 16, float> acc[2][4];
    #pragma unroll
    for (int i = 0; i < 2; i++)
        #pragma unroll
        for (int j = 0; j < 4; j++) wmma::fill_fragment(acc[i][j], 0.0f);

    // per chunk: NTILES tiles of 128 rows x 128B; NTILES*4 cp16 per thread
    auto load_chunk = [&](int ch, int buf) {
        uint32_t sbase = sb + buf * STG;
        #pragma unroll
        for (int t = 0; t < NTILES * 4; t++) {
            int idx  = t * 256 + tid;
            int seg  = idx & 7;
            int row  = idx >> 3;           // 0 .. NTILES*128-1
            int tile = row >> 7;
            int r    = row & 127;
            uint32_t dst = sbase + tile * T_BYTES + r * 144 + seg * 16;
            const char* src = srcs[tile] + (size_t)r * 512 + ch * 128 + seg * 16;
            cp16(dst, src);
        }
        CP_COMMIT();
    };

    load_chunk(0, 0);

    for (int ch = 0; ch < 4; ch++) {
        if (ch < 3) { load_chunk(ch + 1, (ch + 1) & 1); CP_WAIT1(); }
        else        { CP_WAIT0(); }
        __syncthreads();

        const char* stg = smem + (ch & 1) * STG;
        const __half* Ash = (const __half*)stg;
        const __half* Asl = (const __half*)(stg + T_BYTES);
        const __half* Bsh = (const __half*)(stg + (NTILES - 1) * T_BYTES);

        #pragma unroll
        for (int k16 = 0; k16 < 4; k16++) {
            wmma::fragment<wmma::matrix_a, 16, 16, 16, __half, wmma::row_major> fa[2];
            wmma::fragment<wmma::matrix_b, 16, 16, 16, __half, wmma::col_major> fb[4];
            #pragma unroll
            for (int i = 0; i < 2; i++)
                wmma::load_matrix_sync(fa[i], Ash + (wm * 32 + i * 16) * LDS_ELT + k16 * 16, LDS_ELT);
            #pragma unroll
            for (int j = 0; j < 4; j++)
                wmma::load_matrix_sync(fb[j], Bsh + (wn * 64 + j * 16) * LDS_ELT + k16 * 16, LDS_ELT);
            #pragma unroll
            for (int j = 0; j < 4; j++)
                #pragma unroll
                for (int i = 0; i < 2; i++)
                    wmma::mma_sync(acc[i][j], fa[i], fb[j], acc[i][j]);
            if (NT == 2) {
                #pragma unroll
                for (int i = 0; i < 2; i++)
                    wmma::load_matrix_sync(fa[i], Asl + (wm * 32 + i * 16) * LDS_ELT + k16 * 16, LDS_ELT);
                #pragma unroll
                for (int j = 0; j < 4; j++)
                    #pragma unroll
                    for (int i = 0; i < 2; i++)
                        wmma::mma_sync(acc[i][j], fa[i], fb[j], acc[i][j]);
            }
        }
        if (ch < 3) __syncthreads();
    }
    __syncthreads();

    float* Cs = (float*)smem;
    #pragma unroll
    for (int i = 0; i < 2; i++)
        #pragma unroll
        for (int j = 0; j < 4; j++)
            wmma::store_matrix_sync(Cs + (wm * 32 + i * 16) * LDC + wn * 64 + j * 16,
                                    acc[i][j], LDC, wmma::mem_row_major);
    __syncthreads();
}

// ---------------------------------------------------------------------------
// Kernel 4a: Q/K GEMM, fp16 1-term, fp16 output. grid (NP/128, 2, 2)
// ---------------------------------------------------------------------------
__global__ void __launch_bounds__(256, 2) gemm_qk_mma(
    const float* __restrict__ bq, const float* __restrict__ bk)
{
    extern __shared__ char smem[];
    const int m0 = blockIdx.x * 128;
    const int n0 = blockIdx.y * 128;
    const int sel = blockIdx.z;                  // 0=Q, 1=K

    gemm_core_f16<1>(g_a_hf, nullptr, g_w + (size_t)sel * 65536, m0, n0, smem);

    const float* bias = (sel == 0) ? bq : bk;
    __half* out       = (sel == 0) ? g_q : g_k;
    const float scale = (sel == 0) ? QSCALE : 1.0f;
    float* Cs = (float*)smem;

    int half_ = threadIdx.x & 1, mrow = threadIdx.x >> 1;
    __half* op = out + (size_t)(m0 + mrow) * Cc + n0;
    #pragma unroll
    for (int j = 0; j < 16; j++) {
        int n = half_ * 64 + j * 4;
        float v0 = (Cs[mrow * LDC + n + 0] + __ldg(bias + n0 + n + 0)) * scale;
        float v1 = (Cs[mrow * LDC + n + 1] + __ldg(bias + n0 + n + 1)) * scale;
        float v2 = (Cs[mrow * LDC + n + 2] + __ldg(bias + n0 + n + 2)) * scale;
        float v3 = (Cs[mrow * LDC + n + 3] + __ldg(bias + n0 + n + 3)) * scale;
        __half2 p0 = __floats2half2_rn(v0, v1);
        __half2 p1 = __floats2half2_rn(v2, v3);
        uint2 pk = make_uint2(*(uint32_t*)&p0, *(uint32_t*)&p1);
        *(uint2*)(op + n) = pk;
    }
}

// ---------------------------------------------------------------------------
// Kernel 4b: V GEMM, fp16 2-term, fp32 output. grid (NP/128, 2)
// ---------------------------------------------------------------------------
__global__ void __launch_bounds__(256, 2) gemm_v_mma(const float* __restrict__ bv)
{
    extern __shared__ char smem[];
    const int m0 = blockIdx.x * 128;
    const int n0 = blockIdx.y * 128;
    gemm_core_f16<2>(g_a_hf, g_a_lf, g_w + (size_t)2 * 65536, m0, n0, smem);

    float* Cs = (float*)smem;
    int half_ = threadIdx.x & 1, mrow = threadIdx.x >> 1;
    float* op = g_v + (size_t)(m0 + mrow) * Cc + n0;
    #pragma unroll
    for (int j = 0; j < 16; j++) {
        int n = half_ * 64 + j * 4;
        float4 v;
        v.x = Cs[mrow * LDC + n + 0] + __ldg(bv + n0 + n + 0);
        v.y = Cs[mrow * LDC + n + 1] + __ldg(bv + n0 + n + 1);
        v.z = Cs[mrow * LDC + n + 2] + __ldg(bv + n0 + n + 2);
        v.w = Cs[mrow * LDC + n + 3] + __ldg(bv + n0 + n + 3);
        *(float4*)(op + n) = v;
    }
}

// ---------------------------------------------------------------------------
// Kernel 5: 3x3 neighborhood attention. Q/K fp16, V fp32 in; ctx fp16 hi/lo out
// ---------------------------------------------------------------------------
__global__ void __launch_bounds__(256) attn_kernel(
    const float* __restrict__ bk, const float* __restrict__ bv)
{
    int warp = (blockIdx.x * blockDim.x + threadIdx.x) >> 5;
    int lane = threadIdx.x & 31;
    if (warp >= NP) return;
    int b  = warp >> 12;
    int hw = warp & 4095;
    int h = hw >> 6, w = hw & 63;
    int co = lane * 8;

    // load q (8 halves -> 8 floats)
    float qf[8];
    {
        uint4 qv = *(const uint4*)(g_q + (size_t)warp * Cc + co);
        const __half2* qh = (const __half2*)&qv;
        #pragma unroll
        for (int i = 0; i < 4; i++) {
            float2 f = __half22float2(qh[i]);
            qf[2*i] = f.x; qf[2*i+1] = f.y;
        }
    }

    float logits[9];
    #pragma unroll
    for (int n = 0; n < 9; n++) {
        int dh = n / 3 - 1, dw = n % 3 - 1;
        int hh = h + dh, ww = w + dw;
        bool ok = (hh >= 0) & (hh < Hh) & (ww >= 0) & (ww < Ww);
        float d;
        if (ok) {
            uint4 kv = *(const uint4*)(g_k + (size_t)((b << 12) + (hh << 6) + ww) * Cc + co);
            const __half2* kh = (const __half2*)&kv;
            d = 0.f;
            #pragma unroll
            for (int i = 0; i < 4; i++) {
                float2 f = __half22float2(kh[i]);
                d = fmaf(qf[2*i], f.x, d);
                d = fmaf(qf[2*i+1], f.y, d);
            }
        } else {
            float4 b0 = *(const float4*)(bk + co);
            float4 b1 = *(const float4*)(bk + co + 4);
            d = qf[0]*b0.x + qf[1]*b0.y + qf[2]*b0.z + qf[3]*b0.w
              + qf[4]*b1.x + qf[5]*b1.y + qf[6]*b1.z + qf[7]*b1.w;
        }
        #pragma unroll
        for (int o = 16; o; o >>= 1) d += __shfl_xor_sync(0xffffffffu, d, o);
        logits[n] = d;
    }

    float mx = logits[0];
    #pragma unroll
    for (int n = 1; n < 9; n++) mx = fmaxf(mx, logits[n]);
    float e[9]; float sum = 0.f;
    #pragma unroll
    for (int n = 0; n < 9; n++) { e[n] = __expf(logits[n] - mx); sum += e[n]; }
    float inv = 1.0f / sum;

    float acc[8] = {0,0,0,0,0,0,0,0};
    #pragma unroll
    for (int n = 0; n < 9; n++) {
        int dh = n / 3 - 1, dw = n % 3 - 1;
        int hh = h + dh, ww = w + dw;
        bool ok = (hh >= 0) & (hh < Hh) & (ww >= 0) & (ww < Ww);
        const float* vp = ok ? (g_v + (size_t)((b << 12) + (hh << 6) + ww) * Cc) : bv;
        float a = e[n] * inv;
        float4 v0 = *(const float4*)(vp + co);
        float4 v1 = *(const float4*)(vp + co + 4);
        acc[0] = fmaf(a, v0.x, acc[0]); acc[1] = fmaf(a, v0.y, acc[1]);
        acc[2] = fmaf(a, v0.z, acc[2]); acc[3] = fmaf(a, v0.w, acc[3]);
        acc[4] = fmaf(a, v1.x, acc[4]); acc[5] = fmaf(a, v1.y, acc[5]);
        acc[6] = fmaf(a, v1.z, acc[6]); acc[7] = fmaf(a, v1.w, acc[7]);
    }

    uint32_t ph[4], pl[4];
    #pragma unroll
    for (int i = 0; i < 4; i++) {
        float a0 = acc[2*i], a1 = acc[2*i+1];
        __half h0 = __float2half_rn(a0), h1 = __float2half_rn(a1);
        __half l0 = __float2half_rn(a0 - __half2float(h0));
        __half l1 = __float2half_rn(a1 - __half2float(h1));
        __half2 hp = __halves2half2(h0, h1);
        __half2 lp = __halves2half2(l0, l1);
        ph[i] = *reinterpret_cast<uint32_t*>(&hp);
        pl[i] = *reinterpret_cast<uint32_t*>(&lp);
    }
    size_t base = (size_t)warp * Cc + co;
    *(uint4*)(g_c_hf + base) = make_uint4(ph[0], ph[1], ph[2], ph[3]);
    *(uint4*)(g_c_lf + base) = make_uint4(pl[0], pl[1], pl[2], pl[3]);
}

// ---------------------------------------------------------------------------
// Kernel 6: output projection GEMM (fp16 2-term), writes NCHW. grid (NP/128, 2)
// ---------------------------------------------------------------------------
__global__ void __launch_bounds__(256, 2) gemm_o_mma(
    const float* __restrict__ bo, float* __restrict__ out)
{
    extern __shared__ char smem[];
    const int m0 = blockIdx.x * 128;
    const int n0 = blockIdx.y * 128;

    gemm_core_f16<2>(g_c_hf, g_c_lf, g_w + (size_t)3 * 65536, m0, n0, smem);

    float* Cs = (float*)smem;
    const int wid = threadIdx.x >> 5, lane = threadIdx.x & 31;
    const int b   = m0 >> 12;
    const int hw0 = m0 & 4095;

    for (int nn = wid; nn < 128; nn += 8) {
        int m = lane * 4;
        float bias = __ldg(bo + n0 + nn);
        float4 v;
        v.x = Cs[(m + 0) * LDC + nn] + bias;
        v.y = Cs[(m + 1) * LDC + nn] + bias;
        v.z = Cs[(m + 2) * LDC + nn] + bias;
        v.w = Cs[(m + 3) * LDC + nn] + bias;
        *(float4*)(out + ((size_t)(b * 256 + n0 + nn)) * HW + hw0 + m) = v;
    }
}

// ---------------------------------------------------------------------------
extern "C" void kernel_launch(void* const* d_in, const int* in_sizes, int n_in,
                              void* d_out, int out_size) {
    const float* x  = (const float*)d_in[0];
    const float* Wq = (const float*)d_in[1];
    const float* bq = (const float*)d_in[2];
    const float* Wk = (const float*)d_in[3];
    const float* bk = (const float*)d_in[4];
    const float* Wv = (const float*)d_in[5];
    const float* bv = (const float*)d_in[6];
    const float* Wo = (const float*)d_in[7];
    const float* bo = (const float*)d_in[8];
    float* out = (float*)d_out;

    static int configured = 0;
    if (!configured) {
        cudaFuncSetAttribute(gemm_qk_mma, cudaFuncAttributeMaxDynamicSharedMemorySize, SM_NT1);
        cudaFuncSetAttribute(gemm_v_mma,  cudaFuncAttributeMaxDynamicSharedMemorySize, SM_NT2);
        cudaFuncSetAttribute(gemm_o_mma,  cudaFuncAttributeMaxDynamicSharedMemorySize, SM_NT2);
        configured = 1;
    }

    ln_stats_kernel<<<Bn * Cc, 256>>>(x);
    ln_norm_t_kernel<<<dim3(HW / 32, Cc / 32, Bn), dim3(32, 32)>>>(x);
    wconv_kernel<<<(4 * Cc * Cc) / 256, 256>>>(Wq, Wk, Wv, Wo);
    gemm_qk_mma<<<dim3(NP / 128, 2, 2), 256, SM_NT1>>>(bq, bk);
    gemm_v_mma<<<dim3(NP / 128, 2), 256, SM_NT2>>>(bv);
    attn_kernel<<<NP / 8, 256>>>(bk, bv);
    gemm_o_mma<<<dim3(NP / 128, 2), 256, SM_NT2>>>(bo, out);
}

// round 14
// speedup vs baseline: 1.4611x; 1.0482x over previous
#include <cuda_runtime.h>
#include <cuda_bf16.h>
#include <cuda_fp16.h>
#include <mma.h>
#include <cstdint>

using namespace nvcuda;

#define Bn   4
#define Cc   256
#define Hh   64
#define Ww   64
#define HW   4096
#define NP   16384
#define EPSV 1e-5f
#define QSCALE 0.0625f

// ---------------------------------------------------------------------------
// Scratch
// ---------------------------------------------------------------------------
__device__ __half g_q[NP * Cc];        // Q fp16 (scaled, biased)
__device__ __half g_k[NP * Cc];        // K fp16
__device__ float  g_v[NP * Cc];        // V fp32
__device__ __half g_a_hf[NP * Cc];     // normalized input NHWC, fp16 hi
__device__ __half g_a_lf[NP * Cc];     // fp16 lo residual
__device__ __half g_c_hf[NP * Cc];     // attention ctx fp16 hi
__device__ __half g_c_lf[NP * Cc];     // ctx fp16 lo
__device__ __half g_w[4 * Cc * Cc];    // Wq,Wk,Wv,Wo fp16
__device__ float g_mean[Bn * Cc];
__device__ float g_rstd[Bn * Cc];

// ---------------------------------------------------------------------------
__device__ __forceinline__ uint32_t smem_u32(const void* p) {
    uint32_t a;
    asm("{ .reg .u64 t; cvta.to.shared.u64 t, %1; cvt.u32.u64 %0, t; }" : "=r"(a) : "l"(p));
    return a;
}
__device__ __forceinline__ void cp16(uint32_t dst, const void* src) {
    asm volatile("cp.async.ca.shared.global [%0], [%1], 16;" :: "r"(dst), "l"(src));
}
#define CP_COMMIT() asm volatile("cp.async.commit_group;" ::: "memory")
#define CP_WAIT1()  asm volatile("cp.async.wait_group 1;" ::: "memory")
#define CP_WAIT0()  asm volatile("cp.async.wait_group 0;" ::: "memory")

// ---------------------------------------------------------------------------
// Kernel 1: per-(b,c)-plane mean / rstd
// ---------------------------------------------------------------------------
__global__ void ln_stats_kernel(const float* __restrict__ x) {
    int plane = blockIdx.x;
    const float* p = x + (size_t)plane * HW;
    float s = 0.f, ss = 0.f;
    for (int i = threadIdx.x; i < HW; i += 256) {
        float v = p[i];
        s += v; ss += v * v;
    }
    #pragma unroll
    for (int o = 16; o; o >>= 1) {
        s  += __shfl_xor_sync(0xffffffffu, s,  o);
        ss += __shfl_xor_sync(0xffffffffu, ss, o);
    }
    __shared__ float sh1[8], sh2[8];
    int wid = threadIdx.x >> 5, ln = threadIdx.x & 31;
    if (ln == 0) { sh1[wid] = s; sh2[wid] = ss; }
    __syncthreads();
    if (threadIdx.x < 8) {
        s = sh1[threadIdx.x]; ss = sh2[threadIdx.x];
        #pragma unroll
        for (int o = 4; o; o >>= 1) {
            s  += __shfl_xor_sync(0xffu, s,  o);
            ss += __shfl_xor_sync(0xffu, ss, o);
        }
        if (threadIdx.x == 0) {
            float mu  = s * (1.0f / HW);
            float var = ss * (1.0f / HW) - mu * mu;
            g_mean[plane] = mu;
            g_rstd[plane] = rsqrtf(var + EPSV);
        }
    }
}

// ---------------------------------------------------------------------------
// Kernel 2: normalize + transpose NCHW -> NHWC, emit fp16 hi/lo
// ---------------------------------------------------------------------------
__global__ void ln_norm_t_kernel(const float* __restrict__ x) {
    __shared__ float t[32][33];
    int b   = blockIdx.z;
    int c0  = blockIdx.y * 32;
    int hw0 = blockIdx.x * 32;
    int plane = b * Cc + c0 + threadIdx.y;
    float v = x[(size_t)plane * HW + hw0 + threadIdx.x];
    v = (v - g_mean[plane]) * g_rstd[plane];
    t[threadIdx.y][threadIdx.x] = v;
    __syncthreads();
    float o = t[threadIdx.x][threadIdx.y];
    size_t idx = ((size_t)(b * HW + hw0 + threadIdx.y)) * Cc + c0 + threadIdx.x;
    __half h = __float2half_rn(o);
    g_a_hf[idx] = h;
    g_a_lf[idx] = __float2half_rn(o - __half2float(h));
}

// ---------------------------------------------------------------------------
// Kernel 3: weight conversion: all 4 weights -> fp16
// ---------------------------------------------------------------------------
__global__ void wconv_kernel(const float* __restrict__ Wq, const float* __restrict__ Wk,
                             const float* __restrict__ Wv, const float* __restrict__ Wo) {
    int idx = blockIdx.x * 256 + threadIdx.x;
    int sel = idx >> 16, off = idx & 65535;
    const float* W = (sel == 0) ? Wq : (sel == 1) ? Wk : (sel == 2) ? Wv : Wo;
    g_w[idx] = __float2half_rn(W[off]);
}

// ===========================================================================
// fp16 GEMM core, 4 warps, 64x64 warp tiles (2x2).
// NT terms (1: Ah*B ; 2: (Ah+Al)*B, B frags reused across both sweeps).
// C[128x128] over K=256 in 4 chunks of K=64. 2-stage cp.async pipeline.
// Result left in smem Cs[128][132] fp32.
// ===========================================================================
#define LDS_ELT 72                         // halves per staged row (64 + 8 pad)
#define T_BYTES (128 * LDS_ELT * 2)        // 18432
#define LDC 132
#define SM_NT1 73728                       // 2 stages * 2 tiles (Cs 67584 overlays)
#define SM_NT2 110592                      // 2 stages * 3 tiles

template <int NT>
__device__ __forceinline__ void gemm_core_f16(
    const __half* __restrict__ Ah, const __half* __restrict__ Al,
    const __half* __restrict__ W, int m0, int n0, char* smem)
{
    constexpr int NTILES = NT + 1;
    constexpr int STG = NTILES * T_BYTES;

    const uint32_t sb = smem_u32(smem);
    const int tid = threadIdx.x;          // 0..127
    const int wid = tid >> 5;             // 0..3
    const int wm = wid & 1;               // M half
    const int wn = wid >> 1;              // N half

    const char* srcs[NTILES];
    srcs[0] = (const char*)(Ah + (size_t)m0 * Cc);
    if (NT == 2) srcs[1] = (const char*)(Al + (size_t)m0 * Cc);
    srcs[NTILES - 1] = (const char*)(W + (size_t)n0 * Cc);

    wmma::fragment<wmma::accumulator, 16, 16, 16, float> acc[4][4];
    #pragma unroll
    for (int i = 0; i < 4; i++)
        #pragma unroll
        for (int j = 0; j < 4; j++) wmma::fill_fragment(acc[i][j], 0.0f);

    // per chunk: NTILES tiles of 128 rows x 128B; NTILES*8 cp16 per thread
    auto load_chunk = [&](int ch, int buf) {
        uint32_t sbase = sb + buf * STG;
        #pragma unroll
        for (int t = 0; t < NTILES * 8; t++) {
            int idx  = t * 128 + tid;
            int seg  = idx & 7;
            int row  = idx >> 3;           // 0 .. NTILES*128-1
            int tile = row >> 7;
            int r    = row & 127;
            uint32_t dst = sbase + tile * T_BYTES + r * 144 + seg * 16;
            const char* src = srcs[tile] + (size_t)r * 512 + ch * 128 + seg * 16;
            cp16(dst, src);
        }
        CP_COMMIT();
    };

    load_chunk(0, 0);

    for (int ch = 0; ch < 4; ch++) {
        if (ch < 3) { load_chunk(ch + 1, (ch + 1) & 1); CP_WAIT1(); }
        else        { CP_WAIT0(); }
        __syncthreads();

        const char* stg = smem + (ch & 1) * STG;
        const __half* Ash = (const __half*)stg;
        const __half* Asl = (const __half*)(stg + T_BYTES);
        const __half* Bsh = (const __half*)(stg + (NTILES - 1) * T_BYTES);

        #pragma unroll
        for (int k16 = 0; k16 < 4; k16++) {
            wmma::fragment<wmma::matrix_a, 16, 16, 16, __half, wmma::row_major> fa[4];
            wmma::fragment<wmma::matrix_b, 16, 16, 16, __half, wmma::col_major> fb[4];
            #pragma unroll
            for (int j = 0; j < 4; j++)
                wmma::load_matrix_sync(fb[j], Bsh + (wn * 64 + j * 16) * LDS_ELT + k16 * 16, LDS_ELT);
            #pragma unroll
            for (int i = 0; i < 4; i++)
                wmma::load_matrix_sync(fa[i], Ash + (wm * 64 + i * 16) * LDS_ELT + k16 * 16, LDS_ELT);
            #pragma unroll
            for (int i = 0; i < 4; i++)
                #pragma unroll
                for (int j = 0; j < 4; j++)
                    wmma::mma_sync(acc[i][j], fa[i], fb[j], acc[i][j]);
            if (NT == 2) {
                #pragma unroll
                for (int i = 0; i < 4; i++)
                    wmma::load_matrix_sync(fa[i], Asl + (wm * 64 + i * 16) * LDS_ELT + k16 * 16, LDS_ELT);
                #pragma unroll
                for (int i = 0; i < 4; i++)
                    #pragma unroll
                    for (int j = 0; j < 4; j++)
                        wmma::mma_sync(acc[i][j], fa[i], fb[j], acc[i][j]);
            }
        }
        if (ch < 3) __syncthreads();
    }
    __syncthreads();

    float* Cs = (float*)smem;
    #pragma unroll
    for (int i = 0; i < 4; i++)
        #pragma unroll
        for (int j = 0; j < 4; j++)
            wmma::store_matrix_sync(Cs + (wm * 64 + i * 16) * LDC + wn * 64 + j * 16,
                                    acc[i][j], LDC, wmma::mem_row_major);
    __syncthreads();
}

// ---------------------------------------------------------------------------
// Kernel 4a: Q/K GEMM, fp16 1-term, fp16 output. grid (NP/128, 2, 2), 128 thr
// ---------------------------------------------------------------------------
__global__ void __launch_bounds__(128, 2) gemm_qk_mma(
    const float* __restrict__ bq, const float* __restrict__ bk)
{
    extern __shared__ char smem[];
    const int m0 = blockIdx.x * 128;
    const int n0 = blockIdx.y * 128;
    const int sel = blockIdx.z;                  // 0=Q, 1=K

    gemm_core_f16<1>(g_a_hf, nullptr, g_w + (size_t)sel * 65536, m0, n0, smem);

    const float* bias = (sel == 0) ? bq : bk;
    __half* out       = (sel == 0) ? g_q : g_k;
    const float scale = (sel == 0) ? QSCALE : 1.0f;
    float* Cs = (float*)smem;

    int mrow = threadIdx.x;                      // one row per thread
    __half* op = out + (size_t)(m0 + mrow) * Cc + n0;
    #pragma unroll
    for (int j = 0; j < 32; j++) {
        int n = j * 4;
        float v0 = (Cs[mrow * LDC + n + 0] + __ldg(bias + n0 + n + 0)) * scale;
        float v1 = (Cs[mrow * LDC + n + 1] + __ldg(bias + n0 + n + 1)) * scale;
        float v2 = (Cs[mrow * LDC + n + 2] + __ldg(bias + n0 + n + 2)) * scale;
        float v3 = (Cs[mrow * LDC + n + 3] + __ldg(bias + n0 + n + 3)) * scale;
        __half2 p0 = __floats2half2_rn(v0, v1);
        __half2 p1 = __floats2half2_rn(v2, v3);
        uint2 pk = make_uint2(*(uint32_t*)&p0, *(uint32_t*)&p1);
        *(uint2*)(op + n) = pk;
    }
}

// ---------------------------------------------------------------------------
// Kernel 4b: V GEMM, fp16 2-term, fp32 output. grid (NP/128, 2), 128 thr
// ---------------------------------------------------------------------------
__global__ void __launch_bounds__(128, 2) gemm_v_mma(const float* __restrict__ bv)
{
    extern __shared__ char smem[];
    const int m0 = blockIdx.x * 128;
    const int n0 = blockIdx.y * 128;
    gemm_core_f16<2>(g_a_hf, g_a_lf, g_w + (size_t)2 * 65536, m0, n0, smem);

    float* Cs = (float*)smem;
    int mrow = threadIdx.x;
    float* op = g_v + (size_t)(m0 + mrow) * Cc + n0;
    #pragma unroll
    for (int j = 0; j < 32; j++) {
        int n = j * 4;
        float4 v;
        v.x = Cs[mrow * LDC + n + 0] + __ldg(bv + n0 + n + 0);
        v.y = Cs[mrow * LDC + n + 1] + __ldg(bv + n0 + n + 1);
        v.z = Cs[mrow * LDC + n + 2] + __ldg(bv + n0 + n + 2);
        v.w = Cs[mrow * LDC + n + 3] + __ldg(bv + n0 + n + 3);
        *(float4*)(op + n) = v;
    }
}

// ---------------------------------------------------------------------------
// Kernel 5: 3x3 neighborhood attention. Q/K fp16, V fp32 in; ctx fp16 hi/lo out
// ---------------------------------------------------------------------------
__global__ void __launch_bounds__(256) attn_kernel(
    const float* __restrict__ bk, const float* __restrict__ bv)
{
    int warp = (blockIdx.x * blockDim.x + threadIdx.x) >> 5;
    int lane = threadIdx.x & 31;
    if (warp >= NP) return;
    int b  = warp >> 12;
    int hw = warp & 4095;
    int h = hw >> 6, w = hw & 63;
    int co = lane * 8;

    float qf[8];
    {
        uint4 qv = *(const uint4*)(g_q + (size_t)warp * Cc + co);
        const __half2* qh = (const __half2*)&qv;
        #pragma unroll
        for (int i = 0; i < 4; i++) {
            float2 f = __half22float2(qh[i]);
            qf[2*i] = f.x; qf[2*i+1] = f.y;
        }
    }

    float logits[9];
    #pragma unroll
    for (int n = 0; n < 9; n++) {
        int dh = n / 3 - 1, dw = n % 3 - 1;
        int hh = h + dh, ww = w + dw;
        bool ok = (hh >= 0) & (hh < Hh) & (ww >= 0) & (ww < Ww);
        float d;
        if (ok) {
            uint4 kv = *(const uint4*)(g_k + (size_t)((b << 12) + (hh << 6) + ww) * Cc + co);
            const __half2* kh = (const __half2*)&kv;
            d = 0.f;
            #pragma unroll
            for (int i = 0; i < 4; i++) {
                float2 f = __half22float2(kh[i]);
                d = fmaf(qf[2*i], f.x, d);
                d = fmaf(qf[2*i+1], f.y, d);
            }
        } else {
            float4 b0 = *(const float4*)(bk + co);
            float4 b1 = *(const float4*)(bk + co + 4);
            d = qf[0]*b0.x + qf[1]*b0.y + qf[2]*b0.z + qf[3]*b0.w
              + qf[4]*b1.x + qf[5]*b1.y + qf[6]*b1.z + qf[7]*b1.w;
        }
        #pragma unroll
        for (int o = 16; o; o >>= 1) d += __shfl_xor_sync(0xffffffffu, d, o);
        logits[n] = d;
    }

    float mx = logits[0];
    #pragma unroll
    for (int n = 1; n < 9; n++) mx = fmaxf(mx, logits[n]);
    float e[9]; float sum = 0.f;
    #pragma unroll
    for (int n = 0; n < 9; n++) { e[n] = __expf(logits[n] - mx); sum += e[n]; }
    float inv = 1.0f / sum;

    float acc[8] = {0,0,0,0,0,0,0,0};
    #pragma unroll
    for (int n = 0; n < 9; n++) {
        int dh = n / 3 - 1, dw = n % 3 - 1;
        int hh = h + dh, ww = w + dw;
        bool ok = (hh >= 0) & (hh < Hh) & (ww >= 0) & (ww < Ww);
        const float* vp = ok ? (g_v + (size_t)((b << 12) + (hh << 6) + ww) * Cc) : bv;
        float a = e[n] * inv;
        float4 v0 = *(const float4*)(vp + co);
        float4 v1 = *(const float4*)(vp + co + 4);
        acc[0] = fmaf(a, v0.x, acc[0]); acc[1] = fmaf(a, v0.y, acc[1]);
        acc[2] = fmaf(a, v0.z, acc[2]); acc[3] = fmaf(a, v0.w, acc[3]);
        acc[4] = fmaf(a, v1.x, acc[4]); acc[5] = fmaf(a, v1.y, acc[5]);
        acc[6] = fmaf(a, v1.z, acc[6]); acc[7] = fmaf(a, v1.w, acc[7]);
    }

    uint32_t ph[4], pl[4];
    #pragma unroll
    for (int i = 0; i < 4; i++) {
        float a0 = acc[2*i], a1 = acc[2*i+1];
        __half h0 = __float2half_rn(a0), h1 = __float2half_rn(a1);
        __half l0 = __float2half_rn(a0 - __half2float(h0));
        __half l1 = __float2half_rn(a1 - __half2float(h1));
        __half2 hp = __halves2half2(h0, h1);
        __half2 lp = __halves2half2(l0, l1);
        ph[i] = *reinterpret_cast<uint32_t*>(&hp);
        pl[i] = *reinterpret_cast<uint32_t*>(&lp);
    }
    size_t base = (size_t)warp * Cc + co;
    *(uint4*)(g_c_hf + base) = make_uint4(ph[0], ph[1], ph[2], ph[3]);
    *(uint4*)(g_c_lf + base) = make_uint4(pl[0], pl[1], pl[2], pl[3]);
}

// ---------------------------------------------------------------------------
// Kernel 6: output projection GEMM (fp16 2-term), writes NCHW. grid (NP/128, 2), 128 thr
// ---------------------------------------------------------------------------
__global__ void __launch_bounds__(128, 2) gemm_o_mma(
    const float* __restrict__ bo, float* __restrict__ out)
{
    extern __shared__ char smem[];
    const int m0 = blockIdx.x * 128;
    const int n0 = blockIdx.y * 128;

    gemm_core_f16<2>(g_c_hf, g_c_lf, g_w + (size_t)3 * 65536, m0, n0, smem);

    float* Cs = (float*)smem;
    const int wid = threadIdx.x >> 5, lane = threadIdx.x & 31;
    const int b   = m0 >> 12;
    const int hw0 = m0 & 4095;

    for (int nn = wid; nn < 128; nn += 4) {
        int m = lane * 4;
        float bias = __ldg(bo + n0 + nn);
        float4 v;
        v.x = Cs[(m + 0) * LDC + nn] + bias;
        v.y = Cs[(m + 1) * LDC + nn] + bias;
        v.z = Cs[(m + 2) * LDC + nn] + bias;
        v.w = Cs[(m + 3) * LDC + nn] + bias;
        *(float4*)(out + ((size_t)(b * 256 + n0 + nn)) * HW + hw0 + m) = v;
    }
}

// ---------------------------------------------------------------------------
extern "C" void kernel_launch(void* const* d_in, const int* in_sizes, int n_in,
                              void* d_out, int out_size) {
    const float* x  = (const float*)d_in[0];
    const float* Wq = (const float*)d_in[1];
    const float* bq = (const float*)d_in[2];
    const float* Wk = (const float*)d_in[3];
    const float* bk = (const float*)d_in[4];
    const float* Wv = (const float*)d_in[5];
    const float* bv = (const float*)d_in[6];
    const float* Wo = (const float*)d_in[7];
    const float* bo = (const float*)d_in[8];
    float* out = (float*)d_out;

    static int configured = 0;
    if (!configured) {
        cudaFuncSetAttribute(gemm_qk_mma, cudaFuncAttributeMaxDynamicSharedMemorySize, SM_NT1);
        cudaFuncSetAttribute(gemm_v_mma,  cudaFuncAttributeMaxDynamicSharedMemorySize, SM_NT2);
        cudaFuncSetAttribute(gemm_o_mma,  cudaFuncAttributeMaxDynamicSharedMemorySize, SM_NT2);
        configured = 1;
    }

    ln_stats_kernel<<<Bn * Cc, 256>>>(x);
    ln_norm_t_kernel<<<dim3(HW / 32, Cc / 32, Bn), dim3(32, 32)>>>(x);
    wconv_kernel<<<(4 * Cc * Cc) / 256, 256>>>(Wq, Wk, Wv, Wo);
    gemm_qk_mma<<<dim3(NP / 128, 2, 2), 128, SM_NT1>>>(bq, bk);
    gemm_v_mma<<<dim3(NP / 128, 2), 128, SM_NT2>>>(bv);
    attn_kernel<<<NP / 8, 256>>>(bk, bv);
    gemm_o_mma<<<dim3(NP / 128, 2), 128, SM_NT2>>>(bo, out);
}

// round 15
// speedup vs baseline: 1.5650x; 1.0711x over previous
#include <cuda_runtime.h>
#include <cuda_bf16.h>
#include <cuda_fp16.h>
#include <mma.h>
#include <cstdint>

using namespace nvcuda;

#define Bn   4
#define Cc   256
#define Hh   64
#define Ww   64
#define HW   4096
#define NP   16384
#define EPSV 1e-5f
#define QSCALE 0.0625f

// ---------------------------------------------------------------------------
// Scratch
// ---------------------------------------------------------------------------
__device__ __half g_q[NP * Cc];        // Q fp16 (scaled, biased)
__device__ __half g_k[NP * Cc];        // K fp16
__device__ float  g_v[NP * Cc];        // V fp32
__device__ __half g_a_hf[NP * Cc];     // normalized input NHWC, fp16 hi
__device__ __half g_a_lf[NP * Cc];     // fp16 lo residual
__device__ __half g_c_hf[NP * Cc];     // attention ctx fp16 hi
__device__ __half g_c_lf[NP * Cc];     // ctx fp16 lo
__device__ __half g_w[4 * Cc * Cc];    // Wq,Wk,Wv,Wo fp16
__device__ float g_mean[Bn * Cc];
__device__ float g_rstd[Bn * Cc];

// ---------------------------------------------------------------------------
__device__ __forceinline__ uint32_t smem_u32(const void* p) {
    uint32_t a;
    asm("{ .reg .u64 t; cvta.to.shared.u64 t, %1; cvt.u32.u64 %0, t; }" : "=r"(a) : "l"(p));
    return a;
}
__device__ __forceinline__ void cp16(uint32_t dst, const void* src) {
    asm volatile("cp.async.ca.shared.global [%0], [%1], 16;" :: "r"(dst), "l"(src));
}
#define CP_COMMIT() asm volatile("cp.async.commit_group;" ::: "memory")
#define CP_WAIT1()  asm volatile("cp.async.wait_group 1;" ::: "memory")
#define CP_WAIT0()  asm volatile("cp.async.wait_group 0;" ::: "memory")

// ---------------------------------------------------------------------------
// Kernel 1: per-(b,c)-plane mean / rstd
// ---------------------------------------------------------------------------
__global__ void ln_stats_kernel(const float* __restrict__ x) {
    int plane = blockIdx.x;
    const float* p = x + (size_t)plane * HW;
    float s = 0.f, ss = 0.f;
    for (int i = threadIdx.x; i < HW; i += 256) {
        float v = p[i];
        s += v; ss += v * v;
    }
    #pragma unroll
    for (int o = 16; o; o >>= 1) {
        s  += __shfl_xor_sync(0xffffffffu, s,  o);
        ss += __shfl_xor_sync(0xffffffffu, ss, o);
    }
    __shared__ float sh1[8], sh2[8];
    int wid = threadIdx.x >> 5, ln = threadIdx.x & 31;
    if (ln == 0) { sh1[wid] = s; sh2[wid] = ss; }
    __syncthreads();
    if (threadIdx.x < 8) {
        s = sh1[threadIdx.x]; ss = sh2[threadIdx.x];
        #pragma unroll
        for (int o = 4; o; o >>= 1) {
            s  += __shfl_xor_sync(0xffu, s,  o);
            ss += __shfl_xor_sync(0xffu, ss, o);
        }
        if (threadIdx.x == 0) {
            float mu  = s * (1.0f / HW);
            float var = ss * (1.0f / HW) - mu * mu;
            g_mean[plane] = mu;
            g_rstd[plane] = rsqrtf(var + EPSV);
        }
    }
}

// ---------------------------------------------------------------------------
// Kernel 2: normalize + transpose NCHW -> NHWC, emit fp16 hi/lo
// ---------------------------------------------------------------------------
__global__ void ln_norm_t_kernel(const float* __restrict__ x) {
    __shared__ float t[32][33];
    int b   = blockIdx.z;
    int c0  = blockIdx.y * 32;
    int hw0 = blockIdx.x * 32;
    int plane = b * Cc + c0 + threadIdx.y;
    float v = x[(size_t)plane * HW + hw0 + threadIdx.x];
    v = (v - g_mean[plane]) * g_rstd[plane];
    t[threadIdx.y][threadIdx.x] = v;
    __syncthreads();
    float o = t[threadIdx.x][threadIdx.y];
    size_t idx = ((size_t)(b * HW + hw0 + threadIdx.y)) * Cc + c0 + threadIdx.x;
    __half h = __float2half_rn(o);
    g_a_hf[idx] = h;
    g_a_lf[idx] = __float2half_rn(o - __half2float(h));
}

// ---------------------------------------------------------------------------
// Kernel 3: weight conversion: all 4 weights -> fp16
// ---------------------------------------------------------------------------
__global__ void wconv_kernel(const float* __restrict__ Wq, const float* __restrict__ Wk,
                             const float* __restrict__ Wv, const float* __restrict__ Wo) {
    int idx = blockIdx.x * 256 + threadIdx.x;
    int sel = idx >> 16, off = idx & 65535;
    const float* W = (sel == 0) ? Wq : (sel == 1) ? Wk : (sel == 2) ? Wv : Wo;
    g_w[idx] = __float2half_rn(W[off]);
}

// ===========================================================================
// fp16 GEMM core, 4 warps, 64x64 warp tiles (2x2).
// NT terms (1: Ah*B ; 2: (Ah+Al)*B, B frags reused across both sweeps).
// C[128x128] over K=256 in 4 chunks of K=64. 2-stage cp.async pipeline.
// Result left in smem Cs[128][132] fp32.
// ===========================================================================
#define LDS_ELT 72                         // halves per staged row (64 + 8 pad)
#define T_BYTES (128 * LDS_ELT * 2)        // 18432
#define LDC 132
#define CS_BYTES (128 * LDC * 4)           // 67584
#define SM_NT2 110592                      // 2 stages * 3 tiles

template <int NT>
__device__ __forceinline__ void gemm_core_f16(
    const __half* __restrict__ Ah, const __half* __restrict__ Al,
    const __half* __restrict__ W, int m0, int n0, char* smem)
{
    constexpr int NTILES = NT + 1;
    constexpr int STG = NTILES * T_BYTES;

    const uint32_t sb = smem_u32(smem);
    const int tid = threadIdx.x;          // 0..127
    const int wid = tid >> 5;             // 0..3
    const int wm = wid & 1;               // M half
    const int wn = wid >> 1;              // N half

    const char* srcs[NTILES];
    srcs[0] = (const char*)(Ah + (size_t)m0 * Cc);
    if (NT == 2) srcs[1] = (const char*)(Al + (size_t)m0 * Cc);
    srcs[NTILES - 1] = (const char*)(W + (size_t)n0 * Cc);

    wmma::fragment<wmma::accumulator, 16, 16, 16, float> acc[4][4];
    #pragma unroll
    for (int i = 0; i < 4; i++)
        #pragma unroll
        for (int j = 0; j < 4; j++) wmma::fill_fragment(acc[i][j], 0.0f);

    auto load_chunk = [&](int ch, int buf) {
        uint32_t sbase = sb + buf * STG;
        #pragma unroll
        for (int t = 0; t < NTILES * 8; t++) {
            int idx  = t * 128 + tid;
            int seg  = idx & 7;
            int row  = idx >> 3;           // 0 .. NTILES*128-1
            int tile = row >> 7;
            int r    = row & 127;
            uint32_t dst = sbase + tile * T_BYTES + r * 144 + seg * 16;
            const char* src = srcs[tile] + (size_t)r * 512 + ch * 128 + seg * 16;
            cp16(dst, src);
        }
        CP_COMMIT();
    };

    load_chunk(0, 0);

    for (int ch = 0; ch < 4; ch++) {
        if (ch < 3) { load_chunk(ch + 1, (ch + 1) & 1); CP_WAIT1(); }
        else        { CP_WAIT0(); }
        __syncthreads();

        const char* stg = smem + (ch & 1) * STG;
        const __half* Ash = (const __half*)stg;
        const __half* Asl = (const __half*)(stg + T_BYTES);
        const __half* Bsh = (const __half*)(stg + (NTILES - 1) * T_BYTES);

        #pragma unroll
        for (int k16 = 0; k16 < 4; k16++) {
            wmma::fragment<wmma::matrix_a, 16, 16, 16, __half, wmma::row_major> fa[4];
            wmma::fragment<wmma::matrix_b, 16, 16, 16, __half, wmma::col_major> fb[4];
            #pragma unroll
            for (int j = 0; j < 4; j++)
                wmma::load_matrix_sync(fb[j], Bsh + (wn * 64 + j * 16) * LDS_ELT + k16 * 16, LDS_ELT);
            #pragma unroll
            for (int i = 0; i < 4; i++)
                wmma::load_matrix_sync(fa[i], Ash + (wm * 64 + i * 16) * LDS_ELT + k16 * 16, LDS_ELT);
            #pragma unroll
            for (int i = 0; i < 4; i++)
                #pragma unroll
                for (int j = 0; j < 4; j++)
                    wmma::mma_sync(acc[i][j], fa[i], fb[j], acc[i][j]);
            if (NT == 2) {
                #pragma unroll
                for (int i = 0; i < 4; i++)
                    wmma::load_matrix_sync(fa[i], Asl + (wm * 64 + i * 16) * LDS_ELT + k16 * 16, LDS_ELT);
                #pragma unroll
                for (int i = 0; i < 4; i++)
                    #pragma unroll
                    for (int j = 0; j < 4; j++)
                        wmma::mma_sync(acc[i][j], fa[i], fb[j], acc[i][j]);
            }
        }
        if (ch < 3) __syncthreads();
    }
    __syncthreads();

    float* Cs = (float*)smem;
    #pragma unroll
    for (int i = 0; i < 4; i++)
        #pragma unroll
        for (int j = 0; j < 4; j++)
            wmma::store_matrix_sync(Cs + (wm * 64 + i * 16) * LDC + wn * 64 + j * 16,
                                    acc[i][j], LDC, wmma::mem_row_major);
    // NOTE: no trailing sync here; caller stages bias then syncs once.
}

// Stage bias slice [n0, n0+128) into smem after Cs, then barrier.
__device__ __forceinline__ float* stage_bias(char* smem, const float* bias, int n0) {
    float* bsm = (float*)(smem + CS_BYTES);
    bsm[threadIdx.x] = __ldg(bias + n0 + threadIdx.x);
    __syncthreads();
    return bsm;
}

// ---------------------------------------------------------------------------
// Kernel 4: fused QKV GEMM. grid (NP/128, 2, 3): z=0 Q (1-term), z=1 K (1-term),
// z=2 V (2-term). 128 threads.
// ---------------------------------------------------------------------------
__global__ void __launch_bounds__(128, 2) gemm_qkv_mma(
    const float* __restrict__ bq, const float* __restrict__ bk, const float* __restrict__ bv)
{
    extern __shared__ char smem[];
    const int m0 = blockIdx.x * 128;
    const int n0 = blockIdx.y * 128;
    const int z  = blockIdx.z;
    float* Cs = (float*)smem;
    const int mrow = threadIdx.x;

    if (z < 2) {
        gemm_core_f16<1>(g_a_hf, nullptr, g_w + (size_t)z * 65536, m0, n0, smem);
        const float* bias = (z == 0) ? bq : bk;
        float* bsm = stage_bias(smem, bias, n0);
        __half* out = (z == 0) ? g_q : g_k;
        const float scale = (z == 0) ? QSCALE : 1.0f;
        __half* op = out + (size_t)(m0 + mrow) * Cc + n0;
        const float* csr = Cs + mrow * LDC;
        #pragma unroll
        for (int j = 0; j < 32; j++) {
            int n = j * 4;
            float4 bb = *(const float4*)(bsm + n);     // LDS broadcast
            float4 cv = *(const float4*)(csr + n);
            __half2 p0 = __floats2half2_rn((cv.x + bb.x) * scale, (cv.y + bb.y) * scale);
            __half2 p1 = __floats2half2_rn((cv.z + bb.z) * scale, (cv.w + bb.w) * scale);
            uint2 pk = make_uint2(*(uint32_t*)&p0, *(uint32_t*)&p1);
            *(uint2*)(op + n) = pk;
        }
    } else {
        gemm_core_f16<2>(g_a_hf, g_a_lf, g_w + (size_t)2 * 65536, m0, n0, smem);
        float* bsm = stage_bias(smem, bv, n0);
        float* op = g_v + (size_t)(m0 + mrow) * Cc + n0;
        const float* csr = Cs + mrow * LDC;
        #pragma unroll
        for (int j = 0; j < 32; j++) {
            int n = j * 4;
            float4 bb = *(const float4*)(bsm + n);
            float4 cv = *(const float4*)(csr + n);
            cv.x += bb.x; cv.y += bb.y; cv.z += bb.z; cv.w += bb.w;
            *(float4*)(op + n) = cv;
        }
    }
}

// ---------------------------------------------------------------------------
// Kernel 5: 3x3 neighborhood attention. Q/K fp16, V fp32 in; ctx fp16 hi/lo out
// ---------------------------------------------------------------------------
__global__ void __launch_bounds__(256) attn_kernel(
    const float* __restrict__ bk, const float* __restrict__ bv)
{
    int warp = (blockIdx.x * blockDim.x + threadIdx.x) >> 5;
    int lane = threadIdx.x & 31;
    if (warp >= NP) return;
    int b  = warp >> 12;
    int hw = warp & 4095;
    int h = hw >> 6, w = hw & 63;
    int co = lane * 8;

    float qf[8];
    {
        uint4 qv = *(const uint4*)(g_q + (size_t)warp * Cc + co);
        const __half2* qh = (const __half2*)&qv;
        #pragma unroll
        for (int i = 0; i < 4; i++) {
            float2 f = __half22float2(qh[i]);
            qf[2*i] = f.x; qf[2*i+1] = f.y;
        }
    }

    float logits[9];
    #pragma unroll
    for (int n = 0; n < 9; n++) {
        int dh = n / 3 - 1, dw = n % 3 - 1;
        int hh = h + dh, ww = w + dw;
        bool ok = (hh >= 0) & (hh < Hh) & (ww >= 0) & (ww < Ww);
        float d;
        if (ok) {
            uint4 kv = *(const uint4*)(g_k + (size_t)((b << 12) + (hh << 6) + ww) * Cc + co);
            const __half2* kh = (const __half2*)&kv;
            d = 0.f;
            #pragma unroll
            for (int i = 0; i < 4; i++) {
                float2 f = __half22float2(kh[i]);
                d = fmaf(qf[2*i], f.x, d);
                d = fmaf(qf[2*i+1], f.y, d);
            }
        } else {
            float4 b0 = *(const float4*)(bk + co);
            float4 b1 = *(const float4*)(bk + co + 4);
            d = qf[0]*b0.x + qf[1]*b0.y + qf[2]*b0.z + qf[3]*b0.w
              + qf[4]*b1.x + qf[5]*b1.y + qf[6]*b1.z + qf[7]*b1.w;
        }
        #pragma unroll
        for (int o = 16; o; o >>= 1) d += __shfl_xor_sync(0xffffffffu, d, o);
        logits[n] = d;
    }

    float mx = logits[0];
    #pragma unroll
    for (int n = 1; n < 9; n++) mx = fmaxf(mx, logits[n]);
    float e[9]; float sum = 0.f;
    #pragma unroll
    for (int n = 0; n < 9; n++) { e[n] = __expf(logits[n] - mx); sum += e[n]; }
    float inv = 1.0f / sum;

    float acc[8] = {0,0,0,0,0,0,0,0};
    #pragma unroll
    for (int n = 0; n < 9; n++) {
        int dh = n / 3 - 1, dw = n % 3 - 1;
        int hh = h + dh, ww = w + dw;
        bool ok = (hh >= 0) & (hh < Hh) & (ww >= 0) & (ww < Ww);
        const float* vp = ok ? (g_v + (size_t)((b << 12) + (hh << 6) + ww) * Cc) : bv;
        float a = e[n] * inv;
        float4 v0 = *(const float4*)(vp + co);
        float4 v1 = *(const float4*)(vp + co + 4);
        acc[0] = fmaf(a, v0.x, acc[0]); acc[1] = fmaf(a, v0.y, acc[1]);
        acc[2] = fmaf(a, v0.z, acc[2]); acc[3] = fmaf(a, v0.w, acc[3]);
        acc[4] = fmaf(a, v1.x, acc[4]); acc[5] = fmaf(a, v1.y, acc[5]);
        acc[6] = fmaf(a, v1.z, acc[6]); acc[7] = fmaf(a, v1.w, acc[7]);
    }

    uint32_t ph[4], pl[4];
    #pragma unroll
    for (int i = 0; i < 4; i++) {
        float a0 = acc[2*i], a1 = acc[2*i+1];
        __half h0 = __float2half_rn(a0), h1 = __float2half_rn(a1);
        __half l0 = __float2half_rn(a0 - __half2float(h0));
        __half l1 = __float2half_rn(a1 - __half2float(h1));
        __half2 hp = __halves2half2(h0, h1);
        __half2 lp = __halves2half2(l0, l1);
        ph[i] = *reinterpret_cast<uint32_t*>(&hp);
        pl[i] = *reinterpret_cast<uint32_t*>(&lp);
    }
    size_t base = (size_t)warp * Cc + co;
    *(uint4*)(g_c_hf + base) = make_uint4(ph[0], ph[1], ph[2], ph[3]);
    *(uint4*)(g_c_lf + base) = make_uint4(pl[0], pl[1], pl[2], pl[3]);
}

// ---------------------------------------------------------------------------
// Kernel 6: output projection GEMM (fp16 2-term), writes NCHW coalesced.
// grid (NP/128, 2), 128 thr. Thread-per-row epilogue.
// ---------------------------------------------------------------------------
__global__ void __launch_bounds__(128, 2) gemm_o_mma(
    const float* __restrict__ bo, float* __restrict__ out)
{
    extern __shared__ char smem[];
    const int m0 = blockIdx.x * 128;
    const int n0 = blockIdx.y * 128;

    gemm_core_f16<2>(g_c_hf, g_c_lf, g_w + (size_t)3 * 65536, m0, n0, smem);
    float* bsm = stage_bias(smem, bo, n0);

    float* Cs = (float*)smem;
    const int mrow = threadIdx.x;
    const int b   = m0 >> 12;
    const int hw  = (m0 & 4095) + mrow;
    const float* csr = Cs + mrow * LDC;
    float* op = out + ((size_t)(b * 256 + n0)) * HW + hw;

    #pragma unroll
    for (int j = 0; j < 32; j++) {
        int n = j * 4;
        float4 cv = *(const float4*)(csr + n);     // 4-way conflict max
        float4 bb = *(const float4*)(bsm + n);     // broadcast
        op[(size_t)(n + 0) * HW] = cv.x + bb.x;    // warp-coalesced stores
        op[(size_t)(n + 1) * HW] = cv.y + bb.y;
        op[(size_t)(n + 2) * HW] = cv.z + bb.z;
        op[(size_t)(n + 3) * HW] = cv.w + bb.w;
    }
}

// ---------------------------------------------------------------------------
extern "C" void kernel_launch(void* const* d_in, const int* in_sizes, int n_in,
                              void* d_out, int out_size) {
    const float* x  = (const float*)d_in[0];
    const float* Wq = (const float*)d_in[1];
    const float* bq = (const float*)d_in[2];
    const float* Wk = (const float*)d_in[3];
    const float* bk = (const float*)d_in[4];
    const float* Wv = (const float*)d_in[5];
    const float* bv = (const float*)d_in[6];
    const float* Wo = (const float*)d_in[7];
    const float* bo = (const float*)d_in[8];
    float* out = (float*)d_out;

    static int configured = 0;
    if (!configured) {
        cudaFuncSetAttribute(gemm_qkv_mma, cudaFuncAttributeMaxDynamicSharedMemorySize, SM_NT2);
        cudaFuncSetAttribute(gemm_o_mma,   cudaFuncAttributeMaxDynamicSharedMemorySize, SM_NT2);
        configured = 1;
    }

    ln_stats_kernel<<<Bn * Cc, 256>>>(x);
    ln_norm_t_kernel<<<dim3(HW / 32, Cc / 32, Bn), dim3(32, 32)>>>(x);
    wconv_kernel<<<(4 * Cc * Cc) / 256, 256>>>(Wq, Wk, Wv, Wo);
    gemm_qkv_mma<<<dim3(NP / 128, 2, 3), 128, SM_NT2>>>(bq, bk, bv);
    attn_kernel<<<NP / 8, 256>>>(bk, bv);
    gemm_o_mma<<<dim3(NP / 128, 2), 128, SM_NT2>>>(bo, out);
}

// round 16
// speedup vs baseline: 1.7177x; 1.0976x over previous
#include <cuda_runtime.h>
#include <cuda_bf16.h>
#include <cuda_fp16.h>
#include <mma.h>
#include <cstdint>

using namespace nvcuda;

#define Bn   4
#define Cc   256
#define Hh   64
#define Ww   64
#define HW   4096
#define NP   16384
#define EPSV 1e-5f
#define QSCALE 0.0625f

// ---------------------------------------------------------------------------
// Scratch
// ---------------------------------------------------------------------------
__device__ __half g_q[NP * Cc];        // Q fp16 (scaled, biased)
__device__ __half g_k[NP * Cc];        // K fp16
__device__ __half g_v[NP * Cc];        // V fp16
__device__ __half g_a_hf[NP * Cc];     // normalized input NHWC, fp16 hi
__device__ __half g_a_lf[NP * Cc];     // fp16 lo residual (unused in QKV now; kept for O-path symmetry)
__device__ __half g_c_hf[NP * Cc];     // attention ctx fp16 hi
__device__ __half g_c_lf[NP * Cc];     // ctx fp16 lo
__device__ __half g_w[4 * Cc * Cc];    // Wq,Wk,Wv,Wo fp16
__device__ float g_mean[Bn * Cc];
__device__ float g_rstd[Bn * Cc];

// ---------------------------------------------------------------------------
__device__ __forceinline__ uint32_t smem_u32(const void* p) {
    uint32_t a;
    asm("{ .reg .u64 t; cvta.to.shared.u64 t, %1; cvt.u32.u64 %0, t; }" : "=r"(a) : "l"(p));
    return a;
}
__device__ __forceinline__ void cp16(uint32_t dst, const void* src) {
    asm volatile("cp.async.ca.shared.global [%0], [%1], 16;" :: "r"(dst), "l"(src));
}
#define CP_COMMIT() asm volatile("cp.async.commit_group;" ::: "memory")
#define CP_WAIT1()  asm volatile("cp.async.wait_group 1;" ::: "memory")
#define CP_WAIT0()  asm volatile("cp.async.wait_group 0;" ::: "memory")

// ---------------------------------------------------------------------------
// Kernel 1: per-(b,c)-plane mean / rstd
// ---------------------------------------------------------------------------
__global__ void ln_stats_kernel(const float* __restrict__ x) {
    int plane = blockIdx.x;
    const float* p = x + (size_t)plane * HW;
    float s = 0.f, ss = 0.f;
    for (int i = threadIdx.x; i < HW; i += 256) {
        float v = p[i];
        s += v; ss += v * v;
    }
    #pragma unroll
    for (int o = 16; o; o >>= 1) {
        s  += __shfl_xor_sync(0xffffffffu, s,  o);
        ss += __shfl_xor_sync(0xffffffffu, ss, o);
    }
    __shared__ float sh1[8], sh2[8];
    int wid = threadIdx.x >> 5, ln = threadIdx.x & 31;
    if (ln == 0) { sh1[wid] = s; sh2[wid] = ss; }
    __syncthreads();
    if (threadIdx.x < 8) {
        s = sh1[threadIdx.x]; ss = sh2[threadIdx.x];
        #pragma unroll
        for (int o = 4; o; o >>= 1) {
            s  += __shfl_xor_sync(0xffu, s,  o);
            ss += __shfl_xor_sync(0xffu, ss, o);
        }
        if (threadIdx.x == 0) {
            float mu  = s * (1.0f / HW);
            float var = ss * (1.0f / HW) - mu * mu;
            g_mean[plane] = mu;
            g_rstd[plane] = rsqrtf(var + EPSV);
        }
    }
}

// ---------------------------------------------------------------------------
// Kernel 2: normalize + transpose NCHW -> NHWC, emit fp16 hi/lo
// ---------------------------------------------------------------------------
__global__ void ln_norm_t_kernel(const float* __restrict__ x) {
    __shared__ float t[32][33];
    int b   = blockIdx.z;
    int c0  = blockIdx.y * 32;
    int hw0 = blockIdx.x * 32;
    int plane = b * Cc + c0 + threadIdx.y;
    float v = x[(size_t)plane * HW + hw0 + threadIdx.x];
    v = (v - g_mean[plane]) * g_rstd[plane];
    t[threadIdx.y][threadIdx.x] = v;
    __syncthreads();
    float o = t[threadIdx.x][threadIdx.y];
    size_t idx = ((size_t)(b * HW + hw0 + threadIdx.y)) * Cc + c0 + threadIdx.x;
    __half h = __float2half_rn(o);
    g_a_hf[idx] = h;
    g_a_lf[idx] = __float2half_rn(o - __half2float(h));
}

// ---------------------------------------------------------------------------
// Kernel 3: weight conversion: all 4 weights -> fp16
// ---------------------------------------------------------------------------
__global__ void wconv_kernel(const float* __restrict__ Wq, const float* __restrict__ Wk,
                             const float* __restrict__ Wv, const float* __restrict__ Wo) {
    int idx = blockIdx.x * 256 + threadIdx.x;
    int sel = idx >> 16, off = idx & 65535;
    const float* W = (sel == 0) ? Wq : (sel == 1) ? Wk : (sel == 2) ? Wv : Wo;
    g_w[idx] = __float2half_rn(W[off]);
}

// ===========================================================================
// fp16 GEMM core, 4 warps, 64x64 warp tiles (2x2).
// NT terms (1: Ah*B ; 2: (Ah+Al)*B, B frags reused across both sweeps).
// C[128x128] over K=256 in 4 chunks of K=64. 2-stage cp.async pipeline.
// Result left in smem Cs[128][132] fp32.
// ===========================================================================
#define LDS_ELT 72                         // halves per staged row (64 + 8 pad)
#define T_BYTES (128 * LDS_ELT * 2)        // 18432
#define LDC 132
#define CS_BYTES (128 * LDC * 4)           // 67584
#define SM_NT1 73728                       // 2 stages * 2 tiles (> Cs+bias 68096)
#define SM_NT2 110592                      // 2 stages * 3 tiles

template <int NT>
__device__ __forceinline__ void gemm_core_f16(
    const __half* __restrict__ Ah, const __half* __restrict__ Al,
    const __half* __restrict__ W, int m0, int n0, char* smem)
{
    constexpr int NTILES = NT + 1;
    constexpr int STG = NTILES * T_BYTES;

    const uint32_t sb = smem_u32(smem);
    const int tid = threadIdx.x;          // 0..127
    const int wid = tid >> 5;             // 0..3
    const int wm = wid & 1;               // M half
    const int wn = wid >> 1;              // N half

    const char* srcs[NTILES];
    srcs[0] = (const char*)(Ah + (size_t)m0 * Cc);
    if (NT == 2) srcs[1] = (const char*)(Al + (size_t)m0 * Cc);
    srcs[NTILES - 1] = (const char*)(W + (size_t)n0 * Cc);

    wmma::fragment<wmma::accumulator, 16, 16, 16, float> acc[4][4];
    #pragma unroll
    for (int i = 0; i < 4; i++)
        #pragma unroll
        for (int j = 0; j < 4; j++) wmma::fill_fragment(acc[i][j], 0.0f);

    auto load_chunk = [&](int ch, int buf) {
        uint32_t sbase = sb + buf * STG;
        #pragma unroll
        for (int t = 0; t < NTILES * 8; t++) {
            int idx  = t * 128 + tid;
            int seg  = idx & 7;
            int row  = idx >> 3;           // 0 .. NTILES*128-1
            int tile = row >> 7;
            int r    = row & 127;
            uint32_t dst = sbase + tile * T_BYTES + r * 144 + seg * 16;
            const char* src = srcs[tile] + (size_t)r * 512 + ch * 128 + seg * 16;
            cp16(dst, src);
        }
        CP_COMMIT();
    };

    load_chunk(0, 0);

    for (int ch = 0; ch < 4; ch++) {
        if (ch < 3) { load_chunk(ch + 1, (ch + 1) & 1); CP_WAIT1(); }
        else        { CP_WAIT0(); }
        __syncthreads();

        const char* stg = smem + (ch & 1) * STG;
        const __half* Ash = (const __half*)stg;
        const __half* Asl = (const __half*)(stg + T_BYTES);
        const __half* Bsh = (const __half*)(stg + (NTILES - 1) * T_BYTES);

        #pragma unroll
        for (int k16 = 0; k16 < 4; k16++) {
            wmma::fragment<wmma::matrix_a, 16, 16, 16, __half, wmma::row_major> fa[4];
            wmma::fragment<wmma::matrix_b, 16, 16, 16, __half, wmma::col_major> fb[4];
            #pragma unroll
            for (int j = 0; j < 4; j++)
                wmma::load_matrix_sync(fb[j], Bsh + (wn * 64 + j * 16) * LDS_ELT + k16 * 16, LDS_ELT);
            #pragma unroll
            for (int i = 0; i < 4; i++)
                wmma::load_matrix_sync(fa[i], Ash + (wm * 64 + i * 16) * LDS_ELT + k16 * 16, LDS_ELT);
            #pragma unroll
            for (int i = 0; i < 4; i++)
                #pragma unroll
                for (int j = 0; j < 4; j++)
                    wmma::mma_sync(acc[i][j], fa[i], fb[j], acc[i][j]);
            if (NT == 2) {
                #pragma unroll
                for (int i = 0; i < 4; i++)
                    wmma::load_matrix_sync(fa[i], Asl + (wm * 64 + i * 16) * LDS_ELT + k16 * 16, LDS_ELT);
                #pragma unroll
                for (int i = 0; i < 4; i++)
                    #pragma unroll
                    for (int j = 0; j < 4; j++)
                        wmma::mma_sync(acc[i][j], fa[i], fb[j], acc[i][j]);
            }
        }
        if (ch < 3) __syncthreads();
    }
    __syncthreads();

    float* Cs = (float*)smem;
    #pragma unroll
    for (int i = 0; i < 4; i++)
        #pragma unroll
        for (int j = 0; j < 4; j++)
            wmma::store_matrix_sync(Cs + (wm * 64 + i * 16) * LDC + wn * 64 + j * 16,
                                    acc[i][j], LDC, wmma::mem_row_major);
    // NOTE: no trailing sync; caller stages bias then syncs once.
}

// Stage bias slice [n0, n0+128) into smem after Cs, then barrier.
__device__ __forceinline__ float* stage_bias(char* smem, const float* bias, int n0) {
    float* bsm = (float*)(smem + CS_BYTES);
    bsm[threadIdx.x] = __ldg(bias + n0 + threadIdx.x);
    __syncthreads();
    return bsm;
}

// ---------------------------------------------------------------------------
// Kernel 4: fused QKV GEMM (all fp16 1-term, fp16 out).
// grid (NP/128, 2, 3): z=0 Q, z=1 K, z=2 V. 128 threads.
// ---------------------------------------------------------------------------
__global__ void __launch_bounds__(128, 2) gemm_qkv_mma(
    const float* __restrict__ bq, const float* __restrict__ bk, const float* __restrict__ bv)
{
    extern __shared__ char smem[];
    const int m0 = blockIdx.x * 128;
    const int n0 = blockIdx.y * 128;
    const int z  = blockIdx.z;
    float* Cs = (float*)smem;
    const int mrow = threadIdx.x;

    gemm_core_f16<1>(g_a_hf, nullptr, g_w + (size_t)z * 65536, m0, n0, smem);

    const float* bias = (z == 0) ? bq : (z == 1) ? bk : bv;
    float* bsm = stage_bias(smem, bias, n0);
    __half* out = (z == 0) ? g_q : (z == 1) ? g_k : g_v;
    const float scale = (z == 0) ? QSCALE : 1.0f;

    __half* op = out + (size_t)(m0 + mrow) * Cc + n0;
    const float* csr = Cs + mrow * LDC;
    #pragma unroll
    for (int j = 0; j < 32; j++) {
        int n = j * 4;
        float4 bb = *(const float4*)(bsm + n);     // LDS broadcast
        float4 cv = *(const float4*)(csr + n);
        __half2 p0 = __floats2half2_rn((cv.x + bb.x) * scale, (cv.y + bb.y) * scale);
        __half2 p1 = __floats2half2_rn((cv.z + bb.z) * scale, (cv.w + bb.w) * scale);
        uint2 pk = make_uint2(*(uint32_t*)&p0, *(uint32_t*)&p1);
        *(uint2*)(op + n) = pk;
    }
}

// ---------------------------------------------------------------------------
// Kernel 5: 3x3 neighborhood attention. Q/K/V fp16 in; ctx fp16 hi/lo out
// ---------------------------------------------------------------------------
__global__ void __launch_bounds__(256) attn_kernel(
    const float* __restrict__ bk, const float* __restrict__ bv)
{
    int warp = (blockIdx.x * blockDim.x + threadIdx.x) >> 5;
    int lane = threadIdx.x & 31;
    if (warp >= NP) return;
    int b  = warp >> 12;
    int hw = warp & 4095;
    int h = hw >> 6, w = hw & 63;
    int co = lane * 8;

    float qf[8];
    {
        uint4 qv = *(const uint4*)(g_q + (size_t)warp * Cc + co);
        const __half2* qh = (const __half2*)&qv;
        #pragma unroll
        for (int i = 0; i < 4; i++) {
            float2 f = __half22float2(qh[i]);
            qf[2*i] = f.x; qf[2*i+1] = f.y;
        }
    }

    float logits[9];
    #pragma unroll
    for (int n = 0; n < 9; n++) {
        int dh = n / 3 - 1, dw = n % 3 - 1;
        int hh = h + dh, ww = w + dw;
        bool ok = (hh >= 0) & (hh < Hh) & (ww >= 0) & (ww < Ww);
        float d;
        if (ok) {
            uint4 kv = *(const uint4*)(g_k + (size_t)((b << 12) + (hh << 6) + ww) * Cc + co);
            const __half2* kh = (const __half2*)&kv;
            d = 0.f;
            #pragma unroll
            for (int i = 0; i < 4; i++) {
                float2 f = __half22float2(kh[i]);
                d = fmaf(qf[2*i], f.x, d);
                d = fmaf(qf[2*i+1], f.y, d);
            }
        } else {
            float4 b0 = *(const float4*)(bk + co);
            float4 b1 = *(const float4*)(bk + co + 4);
            d = qf[0]*b0.x + qf[1]*b0.y + qf[2]*b0.z + qf[3]*b0.w
              + qf[4]*b1.x + qf[5]*b1.y + qf[6]*b1.z + qf[7]*b1.w;
        }
        #pragma unroll
        for (int o = 16; o; o >>= 1) d += __shfl_xor_sync(0xffffffffu, d, o);
        logits[n] = d;
    }

    float mx = logits[0];
    #pragma unroll
    for (int n = 1; n < 9; n++) mx = fmaxf(mx, logits[n]);
    float e[9]; float sum = 0.f;
    #pragma unroll
    for (int n = 0; n < 9; n++) { e[n] = __expf(logits[n] - mx); sum += e[n]; }
    float inv = 1.0f / sum;

    float acc[8] = {0,0,0,0,0,0,0,0};
    #pragma unroll
    for (int n = 0; n < 9; n++) {
        int dh = n / 3 - 1, dw = n % 3 - 1;
        int hh = h + dh, ww = w + dw;
        bool ok = (hh >= 0) & (hh < Hh) & (ww >= 0) & (ww < Ww);
        float a = e[n] * inv;
        float vf[8];
        if (ok) {
            uint4 vv = *(const uint4*)(g_v + (size_t)((b << 12) + (hh << 6) + ww) * Cc + co);
            const __half2* vh = (const __half2*)&vv;
            #pragma unroll
            for (int i = 0; i < 4; i++) {
                float2 f = __half22float2(vh[i]);
                vf[2*i] = f.x; vf[2*i+1] = f.y;
            }
        } else {
            float4 b0 = *(const float4*)(bv + co);
            float4 b1 = *(const float4*)(bv + co + 4);
            vf[0] = b0.x; vf[1] = b0.y; vf[2] = b0.z; vf[3] = b0.w;
            vf[4] = b1.x; vf[5] = b1.y; vf[6] = b1.z; vf[7] = b1.w;
        }
        #pragma unroll
        for (int i = 0; i < 8; i++) acc[i] = fmaf(a, vf[i], acc[i]);
    }

    uint32_t ph[4], pl[4];
    #pragma unroll
    for (int i = 0; i < 4; i++) {
        float a0 = acc[2*i], a1 = acc[2*i+1];
        __half h0 = __float2half_rn(a0), h1 = __float2half_rn(a1);
        __half l0 = __float2half_rn(a0 - __half2float(h0));
        __half l1 = __float2half_rn(a1 - __half2float(h1));
        __half2 hp = __halves2half2(h0, h1);
        __half2 lp = __halves2half2(l0, l1);
        ph[i] = *reinterpret_cast<uint32_t*>(&hp);
        pl[i] = *reinterpret_cast<uint32_t*>(&lp);
    }
    size_t base = (size_t)warp * Cc + co;
    *(uint4*)(g_c_hf + base) = make_uint4(ph[0], ph[1], ph[2], ph[3]);
    *(uint4*)(g_c_lf + base) = make_uint4(pl[0], pl[1], pl[2], pl[3]);
}

// ---------------------------------------------------------------------------
// Kernel 6: output projection GEMM (fp16 2-term), writes NCHW coalesced.
// grid (NP/128, 2), 128 thr. Thread-per-row epilogue.
// ---------------------------------------------------------------------------
__global__ void __launch_bounds__(128, 2) gemm_o_mma(
    const float* __restrict__ bo, float* __restrict__ out)
{
    extern __shared__ char smem[];
    const int m0 = blockIdx.x * 128;
    const int n0 = blockIdx.y * 128;

    gemm_core_f16<2>(g_c_hf, g_c_lf, g_w + (size_t)3 * 65536, m0, n0, smem);
    float* bsm = stage_bias(smem, bo, n0);

    float* Cs = (float*)smem;
    const int mrow = threadIdx.x;
    const int b   = m0 >> 12;
    const int hw  = (m0 & 4095) + mrow;
    const float* csr = Cs + mrow * LDC;
    float* op = out + ((size_t)(b * 256 + n0)) * HW + hw;

    #pragma unroll
    for (int j = 0; j < 32; j++) {
        int n = j * 4;
        float4 cv = *(const float4*)(csr + n);     // 4-way conflict max
        float4 bb = *(const float4*)(bsm + n);     // broadcast
        op[(size_t)(n + 0) * HW] = cv.x + bb.x;    // warp-coalesced stores
        op[(size_t)(n + 1) * HW] = cv.y + bb.y;
        op[(size_t)(n + 2) * HW] = cv.z + bb.z;
        op[(size_t)(n + 3) * HW] = cv.w + bb.w;
    }
}

// ---------------------------------------------------------------------------
extern "C" void kernel_launch(void* const* d_in, const int* in_sizes, int n_in,
                              void* d_out, int out_size) {
    const float* x  = (const float*)d_in[0];
    const float* Wq = (const float*)d_in[1];
    const float* bq = (const float*)d_in[2];
    const float* Wk = (const float*)d_in[3];
    const float* bk = (const float*)d_in[4];
    const float* Wv = (const float*)d_in[5];
    const float* bv = (const float*)d_in[6];
    const float* Wo = (const float*)d_in[7];
    const float* bo = (const float*)d_in[8];
    float* out = (float*)d_out;

    static int configured = 0;
    if (!configured) {
        cudaFuncSetAttribute(gemm_qkv_mma, cudaFuncAttributeMaxDynamicSharedMemorySize, SM_NT1);
        cudaFuncSetAttribute(gemm_o_mma,   cudaFuncAttributeMaxDynamicSharedMemorySize, SM_NT2);
        configured = 1;
    }

    ln_stats_kernel<<<Bn * Cc, 256>>>(x);
    ln_norm_t_kernel<<<dim3(HW / 32, Cc / 32, Bn), dim3(32, 32)>>>(x);
    wconv_kernel<<<(4 * Cc * Cc) / 256, 256>>>(Wq, Wk, Wv, Wo);
    gemm_qkv_mma<<<dim3(NP / 128, 2, 3), 128, SM_NT1>>>(bq, bk, bv);
    attn_kernel<<<NP / 8, 256>>>(bk, bv);
    gemm_o_mma<<<dim3(NP / 128, 2), 128, SM_NT2>>>(bo, out);
}

// round 17
// speedup vs baseline: 1.9124x; 1.1134x over previous
#include <cuda_runtime.h>
#include <cuda_bf16.h>
#include <cuda_fp16.h>
#include <mma.h>
#include <cstdint>

using namespace nvcuda;

#define Bn   4
#define Cc   256
#define Hh   64
#define Ww   64
#define HW   4096
#define NP   16384
#define EPSV 1e-5f
#define QSCALE 0.0625f

// ---------------------------------------------------------------------------
// Scratch
// ---------------------------------------------------------------------------
__device__ __half g_q[NP * Cc];        // Q fp16 (scaled, biased)
__device__ __half g_k[NP * Cc];        // K fp16
__device__ __half g_v[NP * Cc];        // V fp16
__device__ __half g_a_hf[NP * Cc];     // normalized input NHWC, fp16
__device__ __half g_c_hf[NP * Cc];     // attention ctx fp16
__device__ __half g_w[4 * Cc * Cc];    // Wq,Wk,Wv,Wo fp16
__device__ float g_mean[Bn * Cc];
__device__ float g_rstd[Bn * Cc];

// ---------------------------------------------------------------------------
__device__ __forceinline__ uint32_t smem_u32(const void* p) {
    uint32_t a;
    asm("{ .reg .u64 t; cvta.to.shared.u64 t, %1; cvt.u32.u64 %0, t; }" : "=r"(a) : "l"(p));
    return a;
}
__device__ __forceinline__ void cp16(uint32_t dst, const void* src) {
    asm volatile("cp.async.ca.shared.global [%0], [%1], 16;" :: "r"(dst), "l"(src));
}
#define CP_COMMIT() asm volatile("cp.async.commit_group;" ::: "memory")
#define CP_WAIT1()  asm volatile("cp.async.wait_group 1;" ::: "memory")
#define CP_WAIT0()  asm volatile("cp.async.wait_group 0;" ::: "memory")

// ---------------------------------------------------------------------------
// Kernel 1: per-(b,c)-plane mean / rstd
// ---------------------------------------------------------------------------
__global__ void ln_stats_kernel(const float* __restrict__ x) {
    int plane = blockIdx.x;
    const float* p = x + (size_t)plane * HW;
    float s = 0.f, ss = 0.f;
    for (int i = threadIdx.x; i < HW; i += 256) {
        float v = p[i];
        s += v; ss += v * v;
    }
    #pragma unroll
    for (int o = 16; o; o >>= 1) {
        s  += __shfl_xor_sync(0xffffffffu, s,  o);
        ss += __shfl_xor_sync(0xffffffffu, ss, o);
    }
    __shared__ float sh1[8], sh2[8];
    int wid = threadIdx.x >> 5, ln = threadIdx.x & 31;
    if (ln == 0) { sh1[wid] = s; sh2[wid] = ss; }
    __syncthreads();
    if (threadIdx.x < 8) {
        s = sh1[threadIdx.x]; ss = sh2[threadIdx.x];
        #pragma unroll
        for (int o = 4; o; o >>= 1) {
            s  += __shfl_xor_sync(0xffu, s,  o);
            ss += __shfl_xor_sync(0xffu, ss, o);
        }
        if (threadIdx.x == 0) {
            float mu  = s * (1.0f / HW);
            float var = ss * (1.0f / HW) - mu * mu;
            g_mean[plane] = mu;
            g_rstd[plane] = rsqrtf(var + EPSV);
        }
    }
}

// ---------------------------------------------------------------------------
// Kernel 2: normalize + transpose NCHW -> NHWC, emit fp16
// ---------------------------------------------------------------------------
__global__ void ln_norm_t_kernel(const float* __restrict__ x) {
    __shared__ float t[32][33];
    int b   = blockIdx.z;
    int c0  = blockIdx.y * 32;
    int hw0 = blockIdx.x * 32;
    int plane = b * Cc + c0 + threadIdx.y;
    float v = x[(size_t)plane * HW + hw0 + threadIdx.x];
    v = (v - g_mean[plane]) * g_rstd[plane];
    t[threadIdx.y][threadIdx.x] = v;
    __syncthreads();
    float o = t[threadIdx.x][threadIdx.y];
    size_t idx = ((size_t)(b * HW + hw0 + threadIdx.y)) * Cc + c0 + threadIdx.x;
    g_a_hf[idx] = __float2half_rn(o);
}

// ---------------------------------------------------------------------------
// Kernel 3: weight conversion: all 4 weights -> fp16
// ---------------------------------------------------------------------------
__global__ void wconv_kernel(const float* __restrict__ Wq, const float* __restrict__ Wk,
                             const float* __restrict__ Wv, const float* __restrict__ Wo) {
    int idx = blockIdx.x * 256 + threadIdx.x;
    int sel = idx >> 16, off = idx & 65535;
    const float* W = (sel == 0) ? Wq : (sel == 1) ? Wk : (sel == 2) ? Wv : Wo;
    g_w[idx] = __float2half_rn(W[off]);
}

// ===========================================================================
// fp16 1-term GEMM core, 4 warps, 64x64 warp tiles (2x2).
// C[128x128] = A * B^T over K=256 in 4 chunks of K=64. 2-stage cp.async.
// Result left in smem Cs[128][132] fp32.
// ===========================================================================
#define LDS_ELT 72                         // halves per staged row (64 + 8 pad)
#define T_BYTES (128 * LDS_ELT * 2)        // 18432
#define LDC 132
#define CS_BYTES (128 * LDC * 4)           // 67584
#define SM_NT1 73728                       // 2 stages * 2 tiles (> Cs+bias 68096)

__device__ __forceinline__ void gemm_core_f16(
    const __half* __restrict__ A, const __half* __restrict__ W,
    int m0, int n0, char* smem)
{
    constexpr int STG = 2 * T_BYTES;

    const uint32_t sb = smem_u32(smem);
    const int tid = threadIdx.x;          // 0..127
    const int wid = tid >> 5;             // 0..3
    const int wm = wid & 1;               // M half
    const int wn = wid >> 1;              // N half

    const char* srcs[2] = {
        (const char*)(A + (size_t)m0 * Cc),
        (const char*)(W + (size_t)n0 * Cc)
    };

    wmma::fragment<wmma::accumulator, 16, 16, 16, float> acc[4][4];
    #pragma unroll
    for (int i = 0; i < 4; i++)
        #pragma unroll
        for (int j = 0; j < 4; j++) wmma::fill_fragment(acc[i][j], 0.0f);

    auto load_chunk = [&](int ch, int buf) {
        uint32_t sbase = sb + buf * STG;
        #pragma unroll
        for (int t = 0; t < 16; t++) {
            int idx  = t * 128 + tid;
            int seg  = idx & 7;
            int row  = idx >> 3;           // 0..255
            int tile = row >> 7;
            int r    = row & 127;
            uint32_t dst = sbase + tile * T_BYTES + r * 144 + seg * 16;
            const char* src = srcs[tile] + (size_t)r * 512 + ch * 128 + seg * 16;
            cp16(dst, src);
        }
        CP_COMMIT();
    };

    load_chunk(0, 0);

    for (int ch = 0; ch < 4; ch++) {
        if (ch < 3) { load_chunk(ch + 1, (ch + 1) & 1); CP_WAIT1(); }
        else        { CP_WAIT0(); }
        __syncthreads();

        const char* stg = smem + (ch & 1) * STG;
        const __half* Ash = (const __half*)stg;
        const __half* Bsh = (const __half*)(stg + T_BYTES);

        #pragma unroll
        for (int k16 = 0; k16 < 4; k16++) {
            wmma::fragment<wmma::matrix_a, 16, 16, 16, __half, wmma::row_major> fa[4];
            wmma::fragment<wmma::matrix_b, 16, 16, 16, __half, wmma::col_major> fb[4];
            #pragma unroll
            for (int j = 0; j < 4; j++)
                wmma::load_matrix_sync(fb[j], Bsh + (wn * 64 + j * 16) * LDS_ELT + k16 * 16, LDS_ELT);
            #pragma unroll
            for (int i = 0; i < 4; i++)
                wmma::load_matrix_sync(fa[i], Ash + (wm * 64 + i * 16) * LDS_ELT + k16 * 16, LDS_ELT);
            #pragma unroll
            for (int i = 0; i < 4; i++)
                #pragma unroll
                for (int j = 0; j < 4; j++)
                    wmma::mma_sync(acc[i][j], fa[i], fb[j], acc[i][j]);
        }
        if (ch < 3) __syncthreads();
    }
    __syncthreads();

    float* Cs = (float*)smem;
    #pragma unroll
    for (int i = 0; i < 4; i++)
        #pragma unroll
        for (int j = 0; j < 4; j++)
            wmma::store_matrix_sync(Cs + (wm * 64 + i * 16) * LDC + wn * 64 + j * 16,
                                    acc[i][j], LDC, wmma::mem_row_major);
    // NOTE: no trailing sync; caller stages bias then syncs once.
}

// Stage bias slice [n0, n0+128) into smem after Cs, then barrier.
__device__ __forceinline__ float* stage_bias(char* smem, const float* bias, int n0) {
    float* bsm = (float*)(smem + CS_BYTES);
    bsm[threadIdx.x] = __ldg(bias + n0 + threadIdx.x);
    __syncthreads();
    return bsm;
}

// ---------------------------------------------------------------------------
// Kernel 4: fused QKV GEMM (fp16 1-term, fp16 out).
// grid (NP/128, 2, 3): z=0 Q, z=1 K, z=2 V. 128 threads.
// ---------------------------------------------------------------------------
__global__ void __launch_bounds__(128, 2) gemm_qkv_mma(
    const float* __restrict__ bq, const float* __restrict__ bk, const float* __restrict__ bv)
{
    extern __shared__ char smem[];
    const int m0 = blockIdx.x * 128;
    const int n0 = blockIdx.y * 128;
    const int z  = blockIdx.z;
    float* Cs = (float*)smem;
    const int mrow = threadIdx.x;

    gemm_core_f16(g_a_hf, g_w + (size_t)z * 65536, m0, n0, smem);

    const float* bias = (z == 0) ? bq : (z == 1) ? bk : bv;
    float* bsm = stage_bias(smem, bias, n0);
    __half* out = (z == 0) ? g_q : (z == 1) ? g_k : g_v;
    const float scale = (z == 0) ? QSCALE : 1.0f;

    __half* op = out + (size_t)(m0 + mrow) * Cc + n0;
    const float* csr = Cs + mrow * LDC;
    #pragma unroll
    for (int j = 0; j < 32; j++) {
        int n = j * 4;
        float4 bb = *(const float4*)(bsm + n);     // LDS broadcast
        float4 cv = *(const float4*)(csr + n);
        __half2 p0 = __floats2half2_rn((cv.x + bb.x) * scale, (cv.y + bb.y) * scale);
        __half2 p1 = __floats2half2_rn((cv.z + bb.z) * scale, (cv.w + bb.w) * scale);
        uint2 pk = make_uint2(*(uint32_t*)&p0, *(uint32_t*)&p1);
        *(uint2*)(op + n) = pk;
    }
}

// ---------------------------------------------------------------------------
// Kernel 5: 3x3 neighborhood attention. Q/K/V fp16 in; ctx fp16 out
// ---------------------------------------------------------------------------
__global__ void __launch_bounds__(256) attn_kernel(
    const float* __restrict__ bk, const float* __restrict__ bv)
{
    int warp = (blockIdx.x * blockDim.x + threadIdx.x) >> 5;
    int lane = threadIdx.x & 31;
    if (warp >= NP) return;
    int b  = warp >> 12;
    int hw = warp & 4095;
    int h = hw >> 6, w = hw & 63;
    int co = lane * 8;

    float qf[8];
    {
        uint4 qv = *(const uint4*)(g_q + (size_t)warp * Cc + co);
        const __half2* qh = (const __half2*)&qv;
        #pragma unroll
        for (int i = 0; i < 4; i++) {
            float2 f = __half22float2(qh[i]);
            qf[2*i] = f.x; qf[2*i+1] = f.y;
        }
    }

    float logits[9];
    #pragma unroll
    for (int n = 0; n < 9; n++) {
        int dh = n / 3 - 1, dw = n % 3 - 1;
        int hh = h + dh, ww = w + dw;
        bool ok = (hh >= 0) & (hh < Hh) & (ww >= 0) & (ww < Ww);
        float d;
        if (ok) {
            uint4 kv = *(const uint4*)(g_k + (size_t)((b << 12) + (hh << 6) + ww) * Cc + co);
            const __half2* kh = (const __half2*)&kv;
            d = 0.f;
            #pragma unroll
            for (int i = 0; i < 4; i++) {
                float2 f = __half22float2(kh[i]);
                d = fmaf(qf[2*i], f.x, d);
                d = fmaf(qf[2*i+1], f.y, d);
            }
        } else {
            float4 b0 = *(const float4*)(bk + co);
            float4 b1 = *(const float4*)(bk + co + 4);
            d = qf[0]*b0.x + qf[1]*b0.y + qf[2]*b0.z + qf[3]*b0.w
              + qf[4]*b1.x + qf[5]*b1.y + qf[6]*b1.z + qf[7]*b1.w;
        }
        #pragma unroll
        for (int o = 16; o; o >>= 1) d += __shfl_xor_sync(0xffffffffu, d, o);
        logits[n] = d;
    }

    float mx = logits[0];
    #pragma unroll
    for (int n = 1; n < 9; n++) mx = fmaxf(mx, logits[n]);
    float e[9]; float sum = 0.f;
    #pragma unroll
    for (int n = 0; n < 9; n++) { e[n] = __expf(logits[n] - mx); sum += e[n]; }
    float inv = 1.0f / sum;

    float acc[8] = {0,0,0,0,0,0,0,0};
    #pragma unroll
    for (int n = 0; n < 9; n++) {
        int dh = n / 3 - 1, dw = n % 3 - 1;
        int hh = h + dh, ww = w + dw;
        bool ok = (hh >= 0) & (hh < Hh) & (ww >= 0) & (ww < Ww);
        float a = e[n] * inv;
        float vf[8];
        if (ok) {
            uint4 vv = *(const uint4*)(g_v + (size_t)((b << 12) + (hh << 6) + ww) * Cc + co);
            const __half2* vh = (const __half2*)&vv;
            #pragma unroll
            for (int i = 0; i < 4; i++) {
                float2 f = __half22float2(vh[i]);
                vf[2*i] = f.x; vf[2*i+1] = f.y;
            }
        } else {
            float4 b0 = *(const float4*)(bv + co);
            float4 b1 = *(const float4*)(bv + co + 4);
            vf[0] = b0.x; vf[1] = b0.y; vf[2] = b0.z; vf[3] = b0.w;
            vf[4] = b1.x; vf[5] = b1.y; vf[6] = b1.z; vf[7] = b1.w;
        }
        #pragma unroll
        for (int i = 0; i < 8; i++) acc[i] = fmaf(a, vf[i], acc[i]);
    }

    uint32_t ph[4];
    #pragma unroll
    for (int i = 0; i < 4; i++) {
        __half2 hp = __floats2half2_rn(acc[2*i], acc[2*i+1]);
        ph[i] = *reinterpret_cast<uint32_t*>(&hp);
    }
    *(uint4*)(g_c_hf + (size_t)warp * Cc + co) = make_uint4(ph[0], ph[1], ph[2], ph[3]);
}

// ---------------------------------------------------------------------------
// Kernel 6: output projection GEMM (fp16 1-term), writes NCHW coalesced.
// grid (NP/128, 2), 128 thr. Thread-per-row epilogue.
// ---------------------------------------------------------------------------
__global__ void __launch_bounds__(128, 2) gemm_o_mma(
    const float* __restrict__ bo, float* __restrict__ out)
{
    extern __shared__ char smem[];
    const int m0 = blockIdx.x * 128;
    const int n0 = blockIdx.y * 128;

    gemm_core_f16(g_c_hf, g_w + (size_t)3 * 65536, m0, n0, smem);
    float* bsm = stage_bias(smem, bo, n0);

    float* Cs = (float*)smem;
    const int mrow = threadIdx.x;
    const int b   = m0 >> 12;
    const int hw  = (m0 & 4095) + mrow;
    const float* csr = Cs + mrow * LDC;
    float* op = out + ((size_t)(b * 256 + n0)) * HW + hw;

    #pragma unroll
    for (int j = 0; j < 32; j++) {
        int n = j * 4;
        float4 cv = *(const float4*)(csr + n);     // 4-way conflict max
        float4 bb = *(const float4*)(bsm + n);     // broadcast
        op[(size_t)(n + 0) * HW] = cv.x + bb.x;    // warp-coalesced stores
        op[(size_t)(n + 1) * HW] = cv.y + bb.y;
        op[(size_t)(n + 2) * HW] = cv.z + bb.z;
        op[(size_t)(n + 3) * HW] = cv.w + bb.w;
    }
}

// ---------------------------------------------------------------------------
extern "C" void kernel_launch(void* const* d_in, const int* in_sizes, int n_in,
                              void* d_out, int out_size) {
    const float* x  = (const float*)d_in[0];
    const float* Wq = (const float*)d_in[1];
    const float* bq = (const float*)d_in[2];
    const float* Wk = (const float*)d_in[3];
    const float* bk = (const float*)d_in[4];
    const float* Wv = (const float*)d_in[5];
    const float* bv = (const float*)d_in[6];
    const float* Wo = (const float*)d_in[7];
    const float* bo = (const float*)d_in[8];
    float* out = (float*)d_out;

    static int configured = 0;
    if (!configured) {
        cudaFuncSetAttribute(gemm_qkv_mma, cudaFuncAttributeMaxDynamicSharedMemorySize, SM_NT1);
        cudaFuncSetAttribute(gemm_o_mma,   cudaFuncAttributeMaxDynamicSharedMemorySize, SM_NT1);
        configured = 1;
    }

    ln_stats_kernel<<<Bn * Cc, 256>>>(x);
    ln_norm_t_kernel<<<dim3(HW / 32, Cc / 32, Bn), dim3(32, 32)>>>(x);
    wconv_kernel<<<(4 * Cc * Cc) / 256, 256>>>(Wq, Wk, Wv, Wo);
    gemm_qkv_mma<<<dim3(NP / 128, 2, 3), 128, SM_NT1>>>(bq, bk, bv);
    attn_kernel<<<NP / 8, 256>>>(bk, bv);
    gemm_o_mma<<<dim3(NP / 128, 2), 128, SM_NT1>>>(bo, out);
}